// round 7
// baseline (speedup 1.0000x reference)
#include <cuda_runtime.h>
#include <math.h>

#define BB      2
#define NNODES  512
#define NCGC    64
#define FDIM    128
#define NRBF    20
#define NCONVS  3
#define ETOT    32768
#define BN      (BB*NNODES)      // 1024
#define CUT     5.0f
#define PI_F    3.14159265358979323846f
#define PMSG    4096
#define PCON    1024
#define DMAXC   10.0f

// ---------------- persistent device scratch ----------------
__device__ float  g_h[2][BN*FDIM];
__device__ float4 g_v[2][BN*FDIM];
__device__ float4 g_phi4[BN*FDIM];            // (phi_e0, phi_e1, phi_e2, 0) per (node,f)
__device__ float  g_phic[BN*384];
__device__ float4 g_TmsgA[NCONVS*PMSG*FDIM];  // (w0[p], w0[p+1], w1[p], w1[p+1])
__device__ float2 g_TmsgB[NCONVS*PMSG*FDIM];  // (w2[p], w2[p+1])
__device__ float2 g_Tcon2[NCONVS*PCON*384];
__device__ float  g_ed[ETOT];
__device__ float4 g_un[ETOT];
__device__ int    g_pi[ETOT], g_pj[ETOT];
__device__ int    g_ptrn[BN+1];
__device__ int    g_csr[ETOT];

__device__ __forceinline__ float silu(float x) { return x / (1.f + expf(-x)); }

// ---------------- init (h/v/out) + edge geometry, fused ----------------
__global__ void k_init_geom(const float* __restrict__ h_in, const float* __restrict__ H_in,
                            float* __restrict__ out,
                            const int* __restrict__ nbr, const float* __restrict__ xyz)
{
    int idx = blockIdx.x*blockDim.x + threadIdx.x;   // 32768 threads exactly
    {
        int e = idx;
        int b  = nbr[3*e], ii = nbr[3*e+1], jj = nbr[3*e+2];
        int pi = b*NNODES + ii, pj = b*NNODES + jj;
        g_pi[e] = pi; g_pj[e] = pj;
        float rx = xyz[3*pi]   - xyz[3*pj];
        float ry = xyz[3*pi+1] - xyz[3*pj+1];
        float rz = xyz[3*pi+2] - xyz[3*pj+2];
        float d = sqrtf(rx*rx + ry*ry + rz*rz);
        g_ed[e] = d;
        float inv = 1.f/d;
        g_un[e] = make_float4(rx*inv, ry*inv, rz*inv, 0.f);
    }
    for (int i = idx; i < BN*FDIM; i += ETOT) {
        g_h[0][i] = h_in[i];
        g_v[0][i] = make_float4(0.f,0.f,0.f,0.f);
    }
    for (int i = idx; i < BB*NCGC*FDIM*4; i += ETOT)
        out[i] = (i < BB*NCGC*FDIM) ? H_in[i] : 0.f;
}

// ---------------- count + scan + CSR fill, one block, smem counters ----------------
__global__ void k_scan_fill()
{
    __shared__ int s_cnt[BN];
    __shared__ int s_scan[BN];
    __shared__ int s_fill[BN];
    int t = threadIdx.x;   // 1024
    s_cnt[t] = 0;
    __syncthreads();
    for (int e = t; e < ETOT; e += BN)
        if (g_ed[e] < CUT) atomicAdd(&s_cnt[g_pi[e]], 1);
    __syncthreads();
    s_scan[t] = s_cnt[t];
    __syncthreads();
    for (int off = 1; off < BN; off <<= 1) {
        int x = (t >= off) ? s_scan[t-off] : 0;
        __syncthreads();
        s_scan[t] += x;
        __syncthreads();
    }
    g_ptrn[t+1] = s_scan[t];
    if (t == 0) g_ptrn[0] = 0;
    s_cnt[t] = s_scan[t] - s_cnt[t];
    s_fill[t] = 0;
    __syncthreads();
    for (int e = t; e < ETOT; e += BN) {
        if (g_ed[e] < CUT) {
            int pi = g_pi[e];
            int pos = s_cnt[pi] + atomicAdd(&s_fill[pi], 1);
            g_csr[pos] = e;
        }
    }
}

// ---------------- message table (pair-packed float4/float2, f-indexed) ----------------
__global__ void k_msg_table(const float* __restrict__ We, const float* __restrict__ be)
{
    int p = blockIdx.x, t = blockIdx.y, f = threadIdx.x; // 128 threads
    const float step = CUT/(PMSG-1);
    float d0 = p*step;
    int p1i = (p+1 < PMSG) ? p+1 : PMSG-1;
    float d1 = p1i*step;
    float env0 = (d0 < CUT) ? 0.5f*(cosf(PI_F*d0/CUT) + 1.f) : 0.f;
    float env1 = (d1 < CUT) ? 0.5f*(cosf(PI_F*d1/CUT) + 1.f) : 0.f;
    __shared__ float rb[2][NRBF];
    if (f < 2*NRBF) {
        int which = f/NRBF, k = f%NRBF;
        float d = which ? d1 : d0;
        float dd = fmaxf(d, 1e-6f);
        rb[which][k] = sinf((k+1)*PI_F/CUT*dd)/dd;
    }
    __syncthreads();
    const float* Wt = We + t*NRBF*384;
    const float* bt = be + t*384;
    float b0 = bt[f], b1 = bt[128+f], b2 = bt[256+f];
    float w0p0=b0, w0p1=b0, w1p0=b1, w1p1=b1, w2p0=b2, w2p1=b2;
    #pragma unroll
    for (int k = 0; k < NRBF; k++) {
        float wa = Wt[k*384+f], wb = Wt[k*384+128+f], wc = Wt[k*384+256+f];
        float r0 = rb[0][k], r1 = rb[1][k];
        w0p0 += r0*wa; w0p1 += r1*wa;
        w1p0 += r0*wb; w1p1 += r1*wb;
        w2p0 += r0*wc; w2p1 += r1*wc;
    }
    int o = (t*PMSG+p)*FDIM + f;
    g_TmsgA[o] = make_float4(w0p0*env0, w0p1*env1, w1p0*env0, w1p1*env1);
    g_TmsgB[o] = make_float2(w2p0*env0, w2p1*env1);
}

// ---------------- contraction table (pair-packed, columns remapped to [e3][f]) ----------------
__global__ void k_con_table(const float* __restrict__ Wf)
{
    __shared__ float es[17][FDIM];
    int tid = threadIdx.x;              // 384 threads
    int p0  = blockIdx.x*16, t = blockIdx.y;
    const float step = DMAXC/(PCON-1);
    for (int i = tid; i < 17*FDIM; i += 384) {
        int pl = i / FDIM, k = i % FDIM;
        float d = (p0+pl)*step;
        float o = CUT*k/127.f;
        float x = d - o;
        es[pl][k] = expf(-x*x);
    }
    __syncthreads();
    int src = (tid & 127)*3 + (tid >> 7);
    float acc[17];
    #pragma unroll
    for (int p = 0; p < 17; p++) acc[p] = 0.f;
    const float* Wt = Wf + t*FDIM*384;
    for (int k = 0; k < FDIM; k++) {
        float w = Wt[k*384 + src];
        #pragma unroll
        for (int p = 0; p < 17; p++) acc[p] += es[p][k]*w;
    }
    #pragma unroll
    for (int p = 0; p < 16; p++)
        g_Tcon2[(t*PCON + p0 + p)*384 + tid] = make_float2(acc[p], acc[p+1]);
}

// ---------------- fused 2-layer MLP, 8 nodes/block, 512 threads ----------------
// thread = (node n, g-pair gp); inner loop: float4 h-broadcast + float2 weights
// dynamic smem: ws[16384] | h_s[1024] | hid_s[1024]   (73728 B)
__global__ void __launch_bounds__(512) k_mlp(int hsel,
                      const float* __restrict__ W1, const float* __restrict__ b1,
                      const float* __restrict__ W2, const float* __restrict__ b2, int dst_sel)
{
    extern __shared__ float sm[];
    float* ws    = sm;
    float* h_s   = sm + 16384;
    float* hid_s = sm + 16384 + 1024;
    int t = threadIdx.x;                // 512
    int nb = blockIdx.x*8;
    const float* hb = g_h[hsel];
    for (int i = t; i < 8*FDIM; i += 512)
        h_s[i] = hb[nb*FDIM + i];
    {   // stage W1 (64 KB) as float4, 8 per thread
        const float4* w4 = (const float4*)W1;
        float4* d4 = (float4*)ws;
        #pragma unroll 8
        for (int i = t; i < 4096; i += 512) d4[i] = w4[i];
    }
    __syncthreads();
    int n  = t >> 6;            // 0..7
    int gp = (t & 63) << 1;     // 0,2,...,126
    {
        float a0 = b1[gp], a1 = b1[gp+1];
        #pragma unroll 8
        for (int f = 0; f < FDIM; f += 4) {
            float4 hv = *(const float4*)&h_s[n*FDIM + f];
            float2 w0 = *(const float2*)&ws[(f  )*FDIM + gp];
            float2 w1 = *(const float2*)&ws[(f+1)*FDIM + gp];
            float2 w2 = *(const float2*)&ws[(f+2)*FDIM + gp];
            float2 w3 = *(const float2*)&ws[(f+3)*FDIM + gp];
            a0 += hv.x*w0.x + hv.y*w1.x + hv.z*w2.x + hv.w*w3.x;
            a1 += hv.x*w0.y + hv.y*w1.y + hv.z*w2.y + hv.w*w3.y;
        }
        *(float2*)&hid_s[n*FDIM + gp] = make_float2(silu(a0), silu(a1));
    }
    float A[3][2];
    for (int mm = 0; mm < 3; mm++) {
        __syncthreads();   // protect ws reuse + make hid visible on first pass
        {   // stage W2 chunk mm: ws[k*128+c] = W2[k*384 + mm*128 + c]
            const float4* w24 = (const float4*)W2;   // row stride 96 float4
            float4* ws4 = (float4*)ws;
            #pragma unroll 8
            for (int i = t; i < 4096; i += 512) {
                int k = i >> 5, c = i & 31;
                ws4[i] = w24[k*96 + (mm<<5) + c];
            }
        }
        __syncthreads();
        float a0 = b2[mm*128+gp], a1 = b2[mm*128+gp+1];
        #pragma unroll 8
        for (int k = 0; k < FDIM; k += 4) {
            float4 hv = *(const float4*)&hid_s[n*FDIM + k];
            float2 w0 = *(const float2*)&ws[(k  )*FDIM + gp];
            float2 w1 = *(const float2*)&ws[(k+1)*FDIM + gp];
            float2 w2 = *(const float2*)&ws[(k+2)*FDIM + gp];
            float2 w3 = *(const float2*)&ws[(k+3)*FDIM + gp];
            a0 += hv.x*w0.x + hv.y*w1.x + hv.z*w2.x + hv.w*w3.x;
            a1 += hv.x*w0.y + hv.y*w1.y + hv.z*w2.y + hv.w*w3.y;
        }
        A[mm][0] = a0; A[mm][1] = a1;
    }
    if (dst_sel == 0) {
        // phi4[(node,f)] = (m=f, m=128+f, m=256+f)
        g_phi4[(nb+n)*FDIM + gp]   = make_float4(A[0][0], A[1][0], A[2][0], 0.f);
        g_phi4[(nb+n)*FDIM + gp+1] = make_float4(A[0][1], A[1][1], A[2][1], 0.f);
    } else {
        #pragma unroll
        for (int mm = 0; mm < 3; mm++)
            #pragma unroll
            for (int j = 0; j < 2; j++) {
                int m = mm*128 + gp + j;
                g_phic[(nb+n)*384 + ((m % 3) << 7) + (m / 3)] = A[mm][j];
            }
    }
}

// ---------------- edge message pass: packed table + phi4 ----------------
__global__ void __launch_bounds__(128) k_edge(int t, int cur, int nxt)
{
    int i = blockIdx.x, f = threadIdx.x;
    int e0 = g_ptrn[i], e1 = g_ptrn[i+1];
    const float4* TA = g_TmsgA + (size_t)t*PMSG*FDIM;
    const float2* TB = g_TmsgB + (size_t)t*PMSG*FDIM;
    const float4* vcur = g_v[cur];
    const float inv_step = (PMSG-1)/CUT;
    float acch = 0.f, av0 = 0.f, av1 = 0.f, av2 = 0.f;
    for (int q = e0; q < e1; q++) {
        int e = g_csr[q];
        float d = g_ed[e];
        float u = d*inv_step;
        int idx = (int)u; if (idx > PMSG-2) idx = PMSG-2;
        float fr = u - idx;
        float4 Aq = TA[idx*FDIM + f];
        float2 Bq = TB[idx*FDIM + f];
        float w0 = fmaf(fr, Aq.y - Aq.x, Aq.x);
        float w1 = fmaf(fr, Aq.w - Aq.z, Aq.z);
        float w2 = fmaf(fr, Bq.y - Bq.x, Bq.x);
        int pj = g_pj[e];
        float4 ph = g_phi4[pj*FDIM + f];
        float i0 = ph.x*w0, i1 = ph.y*w1, i2 = ph.z*w2;
        float4 uq = g_un[e];
        float4 vj = vcur[pj*FDIM + f];
        acch += i1;
        av0  += i2*uq.x + i0*vj.x;
        av1  += i2*uq.y + i0*vj.y;
        av2  += i2*uq.z + i0*vj.z;
    }
    g_h[nxt][i*FDIM+f] = g_h[cur][i*FDIM+f] + 0.5f*acch;
    float4 vc = vcur[i*FDIM+f];
    g_v[nxt][i*FDIM+f] = make_float4(vc.x + 0.5f*av0, vc.y + 0.5f*av1, vc.z + 0.5f*av2, 0.f);
}

// ---------------- node update, 8 nodes/block, 512 threads, (n, g-pair) tiling ----------------
// dynamic smem: ws[16384] | h_s[1024] | v_s[1024]f4 | vn_s[1024] | hid_s[1024]  (94208 B)
__global__ void __launch_bounds__(512) k_update(const float* __restrict__ U, const float* __restrict__ Vm,
                         const float* __restrict__ W1, const float* __restrict__ b1,
                         const float* __restrict__ W2, const float* __restrict__ b2, int buf)
{
    extern __shared__ float sm[];
    float*  ws    = sm;
    float*  h_s   = sm + 16384;
    float4* v_s   = (float4*)(sm + 16384 + 1024);
    float*  vn_s  = sm + 16384 + 1024 + 4096;
    float*  hid_s = sm + 16384 + 1024 + 4096 + 1024;
    int t = threadIdx.x;                // 512
    int n  = t >> 6;
    int gp = (t & 63) << 1;
    int nb = blockIdx.x*8;
    float*  hb = g_h[buf];
    float4* vb = g_v[buf];
    for (int i = t; i < 8*FDIM; i += 512) {
        h_s[i] = hb[nb*FDIM + i];
        v_s[i] = vb[nb*FDIM + i];
    }
    // stage U
    {
        const float4* w4 = (const float4*)U;
        float4* d4 = (float4*)ws;
        #pragma unroll 8
        for (int i = t; i < 4096; i += 512) d4[i] = w4[i];
    }
    __syncthreads();
    float au0[3] = {0.f,0.f,0.f}, au1[3] = {0.f,0.f,0.f};
    #pragma unroll 4
    for (int f = 0; f < FDIM; f++) {
        float4 x = v_s[n*FDIM + f];
        float2 u = *(const float2*)&ws[f*FDIM + gp];
        au0[0] += x.x*u.x; au0[1] += x.y*u.x; au0[2] += x.z*u.x;
        au1[0] += x.x*u.y; au1[1] += x.y*u.y; au1[2] += x.z*u.y;
    }
    __syncthreads();
    // stage V
    {
        const float4* w4 = (const float4*)Vm;
        float4* d4 = (float4*)ws;
        #pragma unroll 8
        for (int i = t; i < 4096; i += 512) d4[i] = w4[i];
    }
    __syncthreads();
    float av0[3] = {0.f,0.f,0.f}, av1[3] = {0.f,0.f,0.f};
    #pragma unroll 4
    for (int f = 0; f < FDIM; f++) {
        float4 x = v_s[n*FDIM + f];
        float2 u = *(const float2*)&ws[f*FDIM + gp];
        av0[0] += x.x*u.x; av0[1] += x.y*u.x; av0[2] += x.z*u.x;
        av1[0] += x.x*u.y; av1[1] += x.y*u.y; av1[2] += x.z*u.y;
    }
    float dot0 = au0[0]*av0[0] + au0[1]*av0[1] + au0[2]*av0[2];
    float dot1 = au1[0]*av1[0] + au1[1]*av1[1] + au1[2]*av1[2];
    *(float2*)&vn_s[n*FDIM + gp] = make_float2(
        sqrtf(av0[0]*av0[0] + av0[1]*av0[1] + av0[2]*av0[2] + 1e-15f),
        sqrtf(av1[0]*av1[0] + av1[1]*av1[1] + av1[2]*av1[2] + 1e-15f));
    __syncthreads();
    // stage W1 rows [0,128) (h part)
    {
        const float4* w4 = (const float4*)W1;
        float4* d4 = (float4*)ws;
        #pragma unroll 8
        for (int i = t; i < 4096; i += 512) d4[i] = w4[i];
    }
    __syncthreads();
    float ac0 = b1[gp], ac1 = b1[gp+1];
    #pragma unroll 8
    for (int f = 0; f < FDIM; f += 4) {
        float4 hv = *(const float4*)&h_s[n*FDIM + f];
        float2 w0 = *(const float2*)&ws[(f  )*FDIM + gp];
        float2 w1 = *(const float2*)&ws[(f+1)*FDIM + gp];
        float2 w2 = *(const float2*)&ws[(f+2)*FDIM + gp];
        float2 w3 = *(const float2*)&ws[(f+3)*FDIM + gp];
        ac0 += hv.x*w0.x + hv.y*w1.x + hv.z*w2.x + hv.w*w3.x;
        ac1 += hv.x*w0.y + hv.y*w1.y + hv.z*w2.y + hv.w*w3.y;
    }
    __syncthreads();
    // stage W1 rows [128,256) (vnorm part)
    {
        const float4* w4 = ((const float4*)W1) + 4096;
        float4* d4 = (float4*)ws;
        #pragma unroll 8
        for (int i = t; i < 4096; i += 512) d4[i] = w4[i];
    }
    __syncthreads();
    #pragma unroll 8
    for (int f = 0; f < FDIM; f += 4) {
        float4 hv = *(const float4*)&vn_s[n*FDIM + f];
        float2 w0 = *(const float2*)&ws[(f  )*FDIM + gp];
        float2 w1 = *(const float2*)&ws[(f+1)*FDIM + gp];
        float2 w2 = *(const float2*)&ws[(f+2)*FDIM + gp];
        float2 w3 = *(const float2*)&ws[(f+3)*FDIM + gp];
        ac0 += hv.x*w0.x + hv.y*w1.x + hv.z*w2.x + hv.w*w3.x;
        ac1 += hv.x*w0.y + hv.y*w1.y + hv.z*w2.y + hv.w*w3.y;
    }
    *(float2*)&hid_s[n*FDIM + gp] = make_float2(silu(ac0), silu(ac1));
    float A[3][2];
    for (int mm = 0; mm < 3; mm++) {
        __syncthreads();
        {   // stage W2 chunk mm
            const float4* w24 = (const float4*)W2;   // row stride 96 float4
            float4* ws4 = (float4*)ws;
            #pragma unroll 8
            for (int i = t; i < 4096; i += 512) {
                int k = i >> 5, c = i & 31;
                ws4[i] = w24[k*96 + (mm<<5) + c];
            }
        }
        __syncthreads();
        float a0 = b2[mm*128+gp], a1 = b2[mm*128+gp+1];
        #pragma unroll 8
        for (int k = 0; k < FDIM; k += 4) {
            float4 hv = *(const float4*)&hid_s[n*FDIM + k];
            float2 w0 = *(const float2*)&ws[(k  )*FDIM + gp];
            float2 w1 = *(const float2*)&ws[(k+1)*FDIM + gp];
            float2 w2 = *(const float2*)&ws[(k+2)*FDIM + gp];
            float2 w3 = *(const float2*)&ws[(k+3)*FDIM + gp];
            a0 += hv.x*w0.x + hv.y*w1.x + hv.z*w2.x + hv.w*w3.x;
            a1 += hv.x*w0.y + hv.y*w1.y + hv.z*w2.y + hv.w*w3.y;
        }
        A[mm][0] = a0; A[mm][1] = a1;
    }
    {
        float ds0 = dot0*A[1][0] + A[2][0];
        float ds1 = dot1*A[1][1] + A[2][1];
        int base = (nb+n)*FDIM + gp;
        hb[base]   = h_s[n*FDIM+gp]   + 0.5f*ds0;
        hb[base+1] = h_s[n*FDIM+gp+1] + 0.5f*ds1;
        float4 vo0 = v_s[n*FDIM + gp];
        float4 vo1 = v_s[n*FDIM + gp+1];
        vb[base]   = make_float4(vo0.x + 0.5f*A[0][0]*au0[0],
                                 vo0.y + 0.5f*A[0][0]*au0[1],
                                 vo0.z + 0.5f*A[0][0]*au0[2], 0.f);
        vb[base+1] = make_float4(vo1.x + 0.5f*A[0][1]*au1[0],
                                 vo1.y + 0.5f*A[0][1]*au1[1],
                                 vo1.z + 0.5f*A[0][1]*au1[2], 0.f);
    }
}

// ---------------- contraction: 4 CG sites per block, 16-atom chunks (1024 blocks) ----------------
__global__ void __launch_bounds__(128) k_contract(int t, int buf,
    const float* __restrict__ bf,
    const float* __restrict__ xyz, const float* __restrict__ cgxyz,
    const float* __restrict__ assign, float* __restrict__ out)
{
    int f  = threadIdx.x;
    int b  = blockIdx.x >> 4;
    int cg0 = (blockIdx.x & 15) << 2;
    int a0 = blockIdx.y << 4;                 // 16 atoms per chunk, gridDim.y = 32
    const float2* Tc = g_Tcon2 + (size_t)t*PCON*384;
    const float4* vbuf = g_v[buf];
    float cx[4], cy[4], cz[4];
    #pragma unroll
    for (int c = 0; c < 4; c++) {
        int base = (b*NCGC + cg0 + c)*3;
        cx[c] = cgxyz[base]; cy[c] = cgxyz[base+1]; cz[c] = cgxyz[base+2];
    }
    float bf0 = bf[f*3+0], bf1 = bf[f*3+1], bf2 = bf[f*3+2];
    const float inv_step = (PCON-1)/DMAXC;
    float hacc[4], v0a[4], v1a[4], v2a[4];
    #pragma unroll
    for (int c = 0; c < 4; c++) { hacc[c]=0.f; v0a[c]=0.f; v1a[c]=0.f; v2a[c]=0.f; }
    for (int aa = 0; aa < 16; aa++) {
        int n = b*NNODES + a0 + aa;
        float px = xyz[3*n], py = xyz[3*n+1], pz = xyz[3*n+2];
        const float* pp = g_phic + n*384;
        float f0 = pp[f], f1 = pp[128+f], f2 = pp[256+f];
        float4 vp = vbuf[n*FDIM + f];
        const float* as = assign + n*NCGC + cg0;
        #pragma unroll
        for (int c = 0; c < 4; c++) {
            float rx = px - cx[c], ry = py - cy[c], rz = pz - cz[c];
            float d = sqrtf(rx*rx + ry*ry + rz*rz);
            float inv_d = 1.f/d;
            float s = as[c];
            float td = d*inv_step;
            int idx = (int)td;
            float fr;
            if (idx > PCON-2) { idx = PCON-2; fr = 1.f; } else fr = td - idx;
            const float2* ba = Tc + idx*384;
            float2 q0 = ba[f], q1 = ba[128+f], q2 = ba[256+f];
            float w0 = fmaf(fr, q0.y - q0.x, q0.x) + bf0;
            float w1 = fmaf(fr, q1.y - q1.x, q1.x) + bf1;
            float w2 = fmaf(fr, q2.y - q2.x, q2.x) + bf2;
            float x0 = w0*f0, x1 = w1*f1, x2 = w2*f2;
            hacc[c] += s*x1;
            v0a[c]  += s*(x2*(rx*inv_d) + x0*vp.x);
            v1a[c]  += s*(x2*(ry*inv_d) + x0*vp.y);
            v2a[c]  += s*(x2*(rz*inv_d) + x0*vp.z);
        }
    }
    #pragma unroll
    for (int c = 0; c < 4; c++) {
        int cc = b*NCGC + cg0 + c;
        atomicAdd(&out[cc*FDIM + f], hacc[c]);
        float* vout = out + BB*NCGC*FDIM + (cc*FDIM + f)*3;
        atomicAdd(vout+0, v0a[c]);
        atomicAdd(vout+1, v1a[c]);
        atomicAdd(vout+2, v2a[c]);
    }
}

// ---------------- host ----------------
#define MLP_SMEM (73728)
#define UPD_SMEM (94208)

extern "C" void kernel_launch(void* const* d_in, const int* in_sizes, int n_in,
                              void* d_out, int out_size)
{
    const float* h_in   = (const float*)d_in[0];
    const float* H_in   = (const float*)d_in[1];
    const float* xyz    = (const float*)d_in[2];
    const float* cgxyz  = (const float*)d_in[3];
    const float* assign = (const float*)d_in[4];
    const int*   nbr    = (const int*)  d_in[6];
    const float* msgW1  = (const float*)d_in[7];
    const float* msgb1  = (const float*)d_in[8];
    const float* msgW2  = (const float*)d_in[9];
    const float* msgb2  = (const float*)d_in[10];
    const float* We     = (const float*)d_in[11];
    const float* be     = (const float*)d_in[12];
    const float* updU   = (const float*)d_in[13];
    const float* updV   = (const float*)d_in[14];
    const float* updW1  = (const float*)d_in[15];
    const float* updb1  = (const float*)d_in[16];
    const float* updW2  = (const float*)d_in[17];
    const float* updb2  = (const float*)d_in[18];
    const float* conWf  = (const float*)d_in[19];
    const float* conbf  = (const float*)d_in[20];
    const float* conW1  = (const float*)d_in[21];
    const float* conb1  = (const float*)d_in[22];
    const float* conW2  = (const float*)d_in[23];
    const float* conb2  = (const float*)d_in[24];
    float* out = (float*)d_out;

    cudaFuncSetAttribute(k_mlp,    cudaFuncAttributeMaxDynamicSharedMemorySize, MLP_SMEM);
    cudaFuncSetAttribute(k_update, cudaFuncAttributeMaxDynamicSharedMemorySize, UPD_SMEM);

    k_init_geom<<<ETOT/256, 256>>>(h_in, H_in, out, nbr, xyz);          // 1
    k_scan_fill<<<1, BN>>>();                                            // 2
    {
        dim3 gc(PCON/16, NCONVS);
        k_con_table<<<gc, 384>>>(conWf);                                 // 3
    }
    k_mlp<<<BN/8, 512, MLP_SMEM>>>(0, msgW1, msgb1, msgW2, msgb2, 0);    // 4 (profiled)
    {
        dim3 gm(PMSG, NCONVS);
        k_msg_table<<<gm, 128>>>(We, be);                                // 5
    }

    int cur = 0;
    for (int t = 0; t < NCONVS; t++) {
        int nxt = 1 - cur;
        if (t > 0)
            k_mlp<<<BN/8, 512, MLP_SMEM>>>(cur,
                msgW1 + t*FDIM*FDIM, msgb1 + t*FDIM,
                msgW2 + t*FDIM*384,  msgb2 + t*384, 0);
        k_edge<<<BN, 128>>>(t, cur, nxt);
        k_update<<<BN/8, 512, UPD_SMEM>>>(
            updU + t*FDIM*FDIM, updV + t*FDIM*FDIM,
            updW1 + t*2*FDIM*FDIM, updb1 + t*FDIM,
            updW2 + t*FDIM*384,    updb2 + t*384, nxt);
        k_mlp<<<BN/8, 512, MLP_SMEM>>>(nxt,
            conW1 + t*FDIM*FDIM, conb1 + t*FDIM,
            conW2 + t*FDIM*384,  conb2 + t*384, 1);
        dim3 gk(BB*NCGC/4, 32);
        k_contract<<<gk, 128>>>(t, nxt, conbf + t*384, xyz, cgxyz, assign, out);
        cur = nxt;
    }
    (void)in_sizes; (void)n_in; (void)out_size;
}

// round 9
// speedup vs baseline: 1.0704x; 1.0704x over previous
#include <cuda_runtime.h>
#include <math.h>
#include <stdint.h>

#define BB      2
#define NNODES  512
#define NCGC    64
#define FDIM    128
#define NRBF    20
#define NCONVS  3
#define ETOT    32768
#define BN      (BB*NNODES)      // 1024
#define CUT     5.0f
#define PI_F    3.14159265358979323846f
#define PMSG    4096
#define PCON    1024
#define DMAXC   10.0f

// ---------------- persistent device scratch ----------------
__device__ float  g_h[2][BN*FDIM];
__device__ float4 g_v[2][BN*FDIM];
__device__ float4 g_phi4[BN*FDIM];            // (phi_e0, phi_e1, phi_e2, 0) per (node,f)
__device__ float  g_phic[BN*384];
__device__ float4 g_TmsgA[NCONVS*PMSG*FDIM];  // (w0[p], w0[p+1], w1[p], w1[p+1])
__device__ float2 g_TmsgB[NCONVS*PMSG*FDIM];  // (w2[p], w2[p+1])
__device__ float2 g_Tcon2[NCONVS*PCON*384];
__device__ float  g_ed[ETOT];
__device__ float4 g_un[ETOT];
__device__ int    g_pi[ETOT], g_pj[ETOT];
__device__ int    g_ptrn[BN+1];
__device__ int    g_csr[ETOT];

__device__ __forceinline__ float silu(float x) { return x / (1.f + expf(-x)); }

#define CP_COMMIT() asm volatile("cp.async.commit_group;" ::: "memory")
#define CP_WAIT(n)  asm volatile("cp.async.wait_group %0;" :: "n"(n) : "memory")

// contiguous 64KB (4096 float4) global -> smem via cp.async, 512 threads
__device__ __forceinline__ void stage64(uint32_t sdst, const float4* __restrict__ src, int t)
{
    #pragma unroll
    for (int j = 0; j < 8; j++) {
        int i = t + j*512;
        asm volatile("cp.async.cg.shared.global [%0], [%1], 16;"
                     :: "r"(sdst + i*16), "l"(src + i) : "memory");
    }
}
// W2 chunk mm (128 rows x 128 cols out of 384-col rows) -> smem, 512 threads
__device__ __forceinline__ void stageW2(uint32_t sdst, const float4* __restrict__ W2_4, int mm, int t)
{
    #pragma unroll
    for (int j = 0; j < 8; j++) {
        int i = t + j*512;
        int k = i >> 5, c = i & 31;
        asm volatile("cp.async.cg.shared.global [%0], [%1], 16;"
                     :: "r"(sdst + i*16), "l"(W2_4 + k*96 + mm*32 + c) : "memory");
    }
}

// ---------------- init (h/v/out) + edge geometry, fused ----------------
__global__ void k_init_geom(const float* __restrict__ h_in, const float* __restrict__ H_in,
                            float* __restrict__ out,
                            const int* __restrict__ nbr, const float* __restrict__ xyz)
{
    int idx = blockIdx.x*blockDim.x + threadIdx.x;   // 32768 threads exactly
    {
        int e = idx;
        int b  = nbr[3*e], ii = nbr[3*e+1], jj = nbr[3*e+2];
        int pi = b*NNODES + ii, pj = b*NNODES + jj;
        g_pi[e] = pi; g_pj[e] = pj;
        float rx = xyz[3*pi]   - xyz[3*pj];
        float ry = xyz[3*pi+1] - xyz[3*pj+1];
        float rz = xyz[3*pi+2] - xyz[3*pj+2];
        float d = sqrtf(rx*rx + ry*ry + rz*rz);
        g_ed[e] = d;
        float inv = 1.f/d;
        g_un[e] = make_float4(rx*inv, ry*inv, rz*inv, 0.f);
    }
    for (int i = idx; i < BN*FDIM; i += ETOT) {
        g_h[0][i] = h_in[i];
        g_v[0][i] = make_float4(0.f,0.f,0.f,0.f);
    }
    for (int i = idx; i < BB*NCGC*FDIM*4; i += ETOT)
        out[i] = (i < BB*NCGC*FDIM) ? H_in[i] : 0.f;
}

// ---------------- count + scan + CSR fill, one block, smem counters ----------------
__global__ void k_scan_fill()
{
    __shared__ int s_cnt[BN];
    __shared__ int s_scan[BN];
    __shared__ int s_fill[BN];
    int t = threadIdx.x;   // 1024
    s_cnt[t] = 0;
    __syncthreads();
    for (int e = t; e < ETOT; e += BN)
        if (g_ed[e] < CUT) atomicAdd(&s_cnt[g_pi[e]], 1);
    __syncthreads();
    s_scan[t] = s_cnt[t];
    __syncthreads();
    for (int off = 1; off < BN; off <<= 1) {
        int x = (t >= off) ? s_scan[t-off] : 0;
        __syncthreads();
        s_scan[t] += x;
        __syncthreads();
    }
    g_ptrn[t+1] = s_scan[t];
    if (t == 0) g_ptrn[0] = 0;
    s_cnt[t] = s_scan[t] - s_cnt[t];
    s_fill[t] = 0;
    __syncthreads();
    for (int e = t; e < ETOT; e += BN) {
        if (g_ed[e] < CUT) {
            int pi = g_pi[e];
            int pos = s_cnt[pi] + atomicAdd(&s_fill[pi], 1);
            g_csr[pos] = e;
        }
    }
}

// ---------------- message table (pair-packed float4/float2, f-indexed) ----------------
__global__ void k_msg_table(const float* __restrict__ We, const float* __restrict__ be)
{
    int p = blockIdx.x, t = blockIdx.y, f = threadIdx.x; // 128 threads
    const float step = CUT/(PMSG-1);
    float d0 = p*step;
    int p1i = (p+1 < PMSG) ? p+1 : PMSG-1;
    float d1 = p1i*step;
    float env0 = (d0 < CUT) ? 0.5f*(cosf(PI_F*d0/CUT) + 1.f) : 0.f;
    float env1 = (d1 < CUT) ? 0.5f*(cosf(PI_F*d1/CUT) + 1.f) : 0.f;
    __shared__ float rb[2][NRBF];
    if (f < 2*NRBF) {
        int which = f/NRBF, k = f%NRBF;
        float d = which ? d1 : d0;
        float dd = fmaxf(d, 1e-6f);
        rb[which][k] = sinf((k+1)*PI_F/CUT*dd)/dd;
    }
    __syncthreads();
    const float* Wt = We + t*NRBF*384;
    const float* bt = be + t*384;
    float b0 = bt[f], b1 = bt[128+f], b2 = bt[256+f];
    float w0p0=b0, w0p1=b0, w1p0=b1, w1p1=b1, w2p0=b2, w2p1=b2;
    #pragma unroll
    for (int k = 0; k < NRBF; k++) {
        float wa = Wt[k*384+f], wb = Wt[k*384+128+f], wc = Wt[k*384+256+f];
        float r0 = rb[0][k], r1 = rb[1][k];
        w0p0 += r0*wa; w0p1 += r1*wa;
        w1p0 += r0*wb; w1p1 += r1*wb;
        w2p0 += r0*wc; w2p1 += r1*wc;
    }
    int o = (t*PMSG+p)*FDIM + f;
    g_TmsgA[o] = make_float4(w0p0*env0, w0p1*env1, w1p0*env0, w1p1*env1);
    g_TmsgB[o] = make_float2(w2p0*env0, w2p1*env1);
}

// ---------------- contraction table (pair-packed, columns remapped to [e3][f]) ----------------
__global__ void k_con_table(const float* __restrict__ Wf)
{
    __shared__ float es[17][FDIM];
    int tid = threadIdx.x;              // 384 threads
    int p0  = blockIdx.x*16, t = blockIdx.y;
    const float step = DMAXC/(PCON-1);
    for (int i = tid; i < 17*FDIM; i += 384) {
        int pl = i / FDIM, k = i % FDIM;
        float d = (p0+pl)*step;
        float o = CUT*k/127.f;
        float x = d - o;
        es[pl][k] = expf(-x*x);
    }
    __syncthreads();
    int src = (tid & 127)*3 + (tid >> 7);
    float acc[17];
    #pragma unroll
    for (int p = 0; p < 17; p++) acc[p] = 0.f;
    const float* Wt = Wf + t*FDIM*384;
    for (int k = 0; k < FDIM; k++) {
        float w = Wt[k*384 + src];
        #pragma unroll
        for (int p = 0; p < 17; p++) acc[p] += es[p][k]*w;
    }
    #pragma unroll
    for (int p = 0; p < 16; p++)
        g_Tcon2[(t*PCON + p0 + p)*384 + tid] = make_float2(acc[p], acc[p+1]);
}

// ---------------- fused 2-layer MLP, cp.async triple-buffered weights ----------------
// smem floats: wsW1[16384] | bufA[16384] | bufB[16384] | h_s[1024] | hid_s[1024] = 204800 B
__global__ void __launch_bounds__(512) k_mlp(int hsel,
                      const float* __restrict__ W1, const float* __restrict__ b1,
                      const float* __restrict__ W2, const float* __restrict__ b2, int dst_sel)
{
    extern __shared__ float sm[];
    uint32_t smb = (uint32_t)__cvta_generic_to_shared(sm);
    float* wsW1  = sm;
    float* bufA  = sm + 16384;
    float* bufB  = sm + 32768;
    float* h_s   = sm + 49152;
    float* hid_s = sm + 50176;
    int t = threadIdx.x;                // 512
    int nb = blockIdx.x*8;
    const float4* W2_4 = (const float4*)W2;

    stage64(smb,            (const float4*)W1, t); CP_COMMIT();   // g0 -> wsW1
    stageW2(smb + 16384*4,  W2_4, 0, t);           CP_COMMIT();   // g1 -> bufA
    stageW2(smb + 32768*4,  W2_4, 1, t);           CP_COMMIT();   // g2 -> bufB
    const float* hb = g_h[hsel];
    for (int i = t; i < 8*FDIM; i += 512)
        h_s[i] = hb[nb*FDIM + i];

    CP_WAIT(2);
    __syncthreads();                     // W1 + h ready
    int g = t & 127, n0 = (t >> 7) * 2;
    {
        float bg = b1[g];
        float a0 = bg, a1 = bg;
        #pragma unroll 8
        for (int f = 0; f < FDIM; f += 4) {
            float4 h0 = *(const float4*)&h_s[n0*FDIM + f];
            float4 h1 = *(const float4*)&h_s[(n0+1)*FDIM + f];
            float w0 = wsW1[f*FDIM+g], w1 = wsW1[(f+1)*FDIM+g];
            float w2 = wsW1[(f+2)*FDIM+g], w3 = wsW1[(f+3)*FDIM+g];
            a0 += h0.x*w0 + h0.y*w1 + h0.z*w2 + h0.w*w3;
            a1 += h1.x*w0 + h1.y*w1 + h1.z*w2 + h1.w*w3;
        }
        hid_s[n0*FDIM+g]     = silu(a0);
        hid_s[(n0+1)*FDIM+g] = silu(a1);
    }
    float A[3][2];
    CP_WAIT(1);
    __syncthreads();                     // hid visible + bufA(c0) ready
    {   // chunk0 from bufA
        float b = b2[g];
        float a0 = b, a1 = b;
        #pragma unroll 8
        for (int k = 0; k < FDIM; k += 4) {
            float4 h0 = *(const float4*)&hid_s[n0*FDIM + k];
            float4 h1 = *(const float4*)&hid_s[(n0+1)*FDIM + k];
            float w0 = bufA[k*FDIM+g], w1 = bufA[(k+1)*FDIM+g];
            float w2 = bufA[(k+2)*FDIM+g], w3 = bufA[(k+3)*FDIM+g];
            a0 += h0.x*w0 + h0.y*w1 + h0.z*w2 + h0.w*w3;
            a1 += h1.x*w0 + h1.y*w1 + h1.z*w2 + h1.w*w3;
        }
        A[0][0] = a0; A[0][1] = a1;
    }
    __syncthreads();                     // all done reading bufA
    stageW2(smb + 16384*4, W2_4, 2, t); CP_COMMIT();   // g3 -> bufA
    CP_WAIT(1);
    __syncthreads();                     // bufB(c1) ready
    {   // chunk1 from bufB
        float b = b2[128+g];
        float a0 = b, a1 = b;
        #pragma unroll 8
        for (int k = 0; k < FDIM; k += 4) {
            float4 h0 = *(const float4*)&hid_s[n0*FDIM + k];
            float4 h1 = *(const float4*)&hid_s[(n0+1)*FDIM + k];
            float w0 = bufB[k*FDIM+g], w1 = bufB[(k+1)*FDIM+g];
            float w2 = bufB[(k+2)*FDIM+g], w3 = bufB[(k+3)*FDIM+g];
            a0 += h0.x*w0 + h0.y*w1 + h0.z*w2 + h0.w*w3;
            a1 += h1.x*w0 + h1.y*w1 + h1.z*w2 + h1.w*w3;
        }
        A[1][0] = a0; A[1][1] = a1;
    }
    CP_WAIT(0);
    __syncthreads();                     // bufA(c2) ready
    {   // chunk2 from bufA
        float b = b2[256+g];
        float a0 = b, a1 = b;
        #pragma unroll 8
        for (int k = 0; k < FDIM; k += 4) {
            float4 h0 = *(const float4*)&hid_s[n0*FDIM + k];
            float4 h1 = *(const float4*)&hid_s[(n0+1)*FDIM + k];
            float w0 = bufA[k*FDIM+g], w1 = bufA[(k+1)*FDIM+g];
            float w2 = bufA[(k+2)*FDIM+g], w3 = bufA[(k+3)*FDIM+g];
            a0 += h0.x*w0 + h0.y*w1 + h0.z*w2 + h0.w*w3;
            a1 += h1.x*w0 + h1.y*w1 + h1.z*w2 + h1.w*w3;
        }
        A[2][0] = a0; A[2][1] = a1;
    }
    if (dst_sel == 0) {
        g_phi4[(nb+n0  )*FDIM + g] = make_float4(A[0][0], A[1][0], A[2][0], 0.f);
        g_phi4[(nb+n0+1)*FDIM + g] = make_float4(A[0][1], A[1][1], A[2][1], 0.f);
    } else {
        #pragma unroll
        for (int mm = 0; mm < 3; mm++) {
            int m = mm*128 + g;
            int oi = ((m % 3) << 7) + (m / 3);
            g_phic[(nb+n0  )*384 + oi] = A[mm][0];
            g_phic[(nb+n0+1)*384 + oi] = A[mm][1];
        }
    }
}

// ---------------- edge message pass: packed table + phi4 ----------------
__global__ void __launch_bounds__(128) k_edge(int t, int cur, int nxt)
{
    int i = blockIdx.x, f = threadIdx.x;
    int e0 = g_ptrn[i], e1 = g_ptrn[i+1];
    const float4* TA = g_TmsgA + (size_t)t*PMSG*FDIM;
    const float2* TB = g_TmsgB + (size_t)t*PMSG*FDIM;
    const float4* vcur = g_v[cur];
    const float inv_step = (PMSG-1)/CUT;
    float acch = 0.f, av0 = 0.f, av1 = 0.f, av2 = 0.f;
    for (int q = e0; q < e1; q++) {
        int e = g_csr[q];
        float d = g_ed[e];
        float u = d*inv_step;
        int idx = (int)u; if (idx > PMSG-2) idx = PMSG-2;
        float fr = u - idx;
        float4 Aq = TA[idx*FDIM + f];
        float2 Bq = TB[idx*FDIM + f];
        float w0 = fmaf(fr, Aq.y - Aq.x, Aq.x);
        float w1 = fmaf(fr, Aq.w - Aq.z, Aq.z);
        float w2 = fmaf(fr, Bq.y - Bq.x, Bq.x);
        int pj = g_pj[e];
        float4 ph = g_phi4[pj*FDIM + f];
        float i0 = ph.x*w0, i1 = ph.y*w1, i2 = ph.z*w2;
        float4 uq = g_un[e];
        float4 vj = vcur[pj*FDIM + f];
        acch += i1;
        av0  += i2*uq.x + i0*vj.x;
        av1  += i2*uq.y + i0*vj.y;
        av2  += i2*uq.z + i0*vj.z;
    }
    g_h[nxt][i*FDIM+f] = g_h[cur][i*FDIM+f] + 0.5f*acch;
    float4 vc = vcur[i*FDIM+f];
    g_v[nxt][i*FDIM+f] = make_float4(vc.x + 0.5f*av0, vc.y + 0.5f*av1, vc.z + 0.5f*av2, 0.f);
}

// ---------------- node update: cp.async 3-buffer rotation over 7 weight chunks ----------------
// smem floats: B0[16384] | B1[16384] | B2[16384] | h_s[1024] | v_s[4096] | vn_s[1024] | hid_s[1024]
//            = 56320 floats = 225280 B
__global__ void __launch_bounds__(512) k_update(const float* __restrict__ U, const float* __restrict__ Vm,
                         const float* __restrict__ W1, const float* __restrict__ b1,
                         const float* __restrict__ W2, const float* __restrict__ b2, int buf)
{
    extern __shared__ float sm[];
    uint32_t smb = (uint32_t)__cvta_generic_to_shared(sm);
    float*  B0    = sm;
    float*  B1    = sm + 16384;
    float*  B2    = sm + 32768;
    float*  h_s   = sm + 49152;
    float4* v_s   = (float4*)(sm + 50176);
    float*  vn_s  = sm + 54272;
    float*  hid_s = sm + 55296;
    int t = threadIdx.x;                // 512
    int g = t & 127, n0 = (t >> 7) * 2;
    int nb = blockIdx.x*8;
    float*  hb = g_h[buf];
    float4* vb = g_v[buf];
    const float4* W2_4 = (const float4*)W2;

    stage64(smb,           (const float4*)U,  t); CP_COMMIT();   // g0 -> B0 (U)
    stage64(smb + 16384*4, (const float4*)Vm, t); CP_COMMIT();   // g1 -> B1 (V)
    stage64(smb + 32768*4, (const float4*)W1, t); CP_COMMIT();   // g2 -> B2 (W1a)
    for (int i = t; i < 8*FDIM; i += 512) {
        h_s[i] = hb[nb*FDIM + i];
        v_s[i] = vb[nb*FDIM + i];
    }

    CP_WAIT(2);
    __syncthreads();                     // B0=U, h/v ready
    float au0[3] = {0.f,0.f,0.f}, au1[3] = {0.f,0.f,0.f};
    #pragma unroll 4
    for (int f = 0; f < FDIM; f++) {
        float uu = B0[f*FDIM+g];
        float4 x0 = v_s[n0*FDIM + f];
        float4 x1 = v_s[(n0+1)*FDIM + f];
        au0[0] += x0.x*uu; au0[1] += x0.y*uu; au0[2] += x0.z*uu;
        au1[0] += x1.x*uu; au1[1] += x1.y*uu; au1[2] += x1.z*uu;
    }
    __syncthreads();                     // done reading B0
    stage64(smb, ((const float4*)W1) + 4096, t); CP_COMMIT();    // g3 -> B0 (W1b)
    CP_WAIT(2);
    __syncthreads();                     // B1=V ready
    float av0[3] = {0.f,0.f,0.f}, av1[3] = {0.f,0.f,0.f};
    #pragma unroll 4
    for (int f = 0; f < FDIM; f++) {
        float vv = B1[f*FDIM+g];
        float4 x0 = v_s[n0*FDIM + f];
        float4 x1 = v_s[(n0+1)*FDIM + f];
        av0[0] += x0.x*vv; av0[1] += x0.y*vv; av0[2] += x0.z*vv;
        av1[0] += x1.x*vv; av1[1] += x1.y*vv; av1[2] += x1.z*vv;
    }
    float dot0 = au0[0]*av0[0] + au0[1]*av0[1] + au0[2]*av0[2];
    float dot1 = au1[0]*av1[0] + au1[1]*av1[1] + au1[2]*av1[2];
    vn_s[n0*FDIM + g]     = sqrtf(av0[0]*av0[0] + av0[1]*av0[1] + av0[2]*av0[2] + 1e-15f);
    vn_s[(n0+1)*FDIM + g] = sqrtf(av1[0]*av1[0] + av1[1]*av1[1] + av1[2]*av1[2] + 1e-15f);
    __syncthreads();                     // done reading B1
    stageW2(smb + 16384*4, W2_4, 0, t); CP_COMMIT();             // g4 -> B1 (W2c0)
    CP_WAIT(2);
    __syncthreads();                     // B2=W1a ready
    float ac0 = b1[g], ac1 = ac0;
    #pragma unroll 8
    for (int f = 0; f < FDIM; f += 4) {
        float4 h0 = *(const float4*)&h_s[n0*FDIM + f];
        float4 h1 = *(const float4*)&h_s[(n0+1)*FDIM + f];
        float w0 = B2[f*FDIM+g], w1 = B2[(f+1)*FDIM+g];
        float w2 = B2[(f+2)*FDIM+g], w3 = B2[(f+3)*FDIM+g];
        ac0 += h0.x*w0 + h0.y*w1 + h0.z*w2 + h0.w*w3;
        ac1 += h1.x*w0 + h1.y*w1 + h1.z*w2 + h1.w*w3;
    }
    __syncthreads();                     // done reading B2
    stageW2(smb + 32768*4, W2_4, 1, t); CP_COMMIT();             // g5 -> B2 (W2c1)
    CP_WAIT(2);
    __syncthreads();                     // B0=W1b ready, vn visible
    #pragma unroll 8
    for (int f = 0; f < FDIM; f += 4) {
        float4 h0 = *(const float4*)&vn_s[n0*FDIM + f];
        float4 h1 = *(const float4*)&vn_s[(n0+1)*FDIM + f];
        float w0 = B0[f*FDIM+g], w1 = B0[(f+1)*FDIM+g];
        float w2 = B0[(f+2)*FDIM+g], w3 = B0[(f+3)*FDIM+g];
        ac0 += h0.x*w0 + h0.y*w1 + h0.z*w2 + h0.w*w3;
        ac1 += h1.x*w0 + h1.y*w1 + h1.z*w2 + h1.w*w3;
    }
    hid_s[n0*FDIM+g]     = silu(ac0);
    hid_s[(n0+1)*FDIM+g] = silu(ac1);
    __syncthreads();                     // done reading B0
    stageW2(smb, W2_4, 2, t); CP_COMMIT();                       // g6 -> B0 (W2c2)
    float A[3][2];
    CP_WAIT(2);
    __syncthreads();                     // B1=W2c0 ready, hid visible
    {
        float b = b2[g];
        float a0 = b, a1 = b;
        #pragma unroll 8
        for (int k = 0; k < FDIM; k += 4) {
            float4 h0 = *(const float4*)&hid_s[n0*FDIM + k];
            float4 h1 = *(const float4*)&hid_s[(n0+1)*FDIM + k];
            float w0 = B1[k*FDIM+g], w1 = B1[(k+1)*FDIM+g];
            float w2 = B1[(k+2)*FDIM+g], w3 = B1[(k+3)*FDIM+g];
            a0 += h0.x*w0 + h0.y*w1 + h0.z*w2 + h0.w*w3;
            a1 += h1.x*w0 + h1.y*w1 + h1.z*w2 + h1.w*w3;
        }
        A[0][0] = a0; A[0][1] = a1;
    }
    CP_WAIT(1);
    __syncthreads();                     // B2=W2c1 ready
    {
        float b = b2[128+g];
        float a0 = b, a1 = b;
        #pragma unroll 8
        for (int k = 0; k < FDIM; k += 4) {
            float4 h0 = *(const float4*)&hid_s[n0*FDIM + k];
            float4 h1 = *(const float4*)&hid_s[(n0+1)*FDIM + k];
            float w0 = B2[k*FDIM+g], w1 = B2[(k+1)*FDIM+g];
            float w2 = B2[(k+2)*FDIM+g], w3 = B2[(k+3)*FDIM+g];
            a0 += h0.x*w0 + h0.y*w1 + h0.z*w2 + h0.w*w3;
            a1 += h1.x*w0 + h1.y*w1 + h1.z*w2 + h1.w*w3;
        }
        A[1][0] = a0; A[1][1] = a1;
    }
    CP_WAIT(0);
    __syncthreads();                     // B0=W2c2 ready
    {
        float b = b2[256+g];
        float a0 = b, a1 = b;
        #pragma unroll 8
        for (int k = 0; k < FDIM; k += 4) {
            float4 h0 = *(const float4*)&hid_s[n0*FDIM + k];
            float4 h1 = *(const float4*)&hid_s[(n0+1)*FDIM + k];
            float w0 = B0[k*FDIM+g], w1 = B0[(k+1)*FDIM+g];
            float w2 = B0[(k+2)*FDIM+g], w3 = B0[(k+3)*FDIM+g];
            a0 += h0.x*w0 + h0.y*w1 + h0.z*w2 + h0.w*w3;
            a1 += h1.x*w0 + h1.y*w1 + h1.z*w2 + h1.w*w3;
        }
        A[2][0] = a0; A[2][1] = a1;
    }
    {
        float ds0 = dot0*A[1][0] + A[2][0];
        float ds1 = dot1*A[1][1] + A[2][1];
        hb[(nb+n0  )*FDIM + g] = h_s[n0*FDIM+g]     + 0.5f*ds0;
        hb[(nb+n0+1)*FDIM + g] = h_s[(n0+1)*FDIM+g] + 0.5f*ds1;
        float4 vo0 = v_s[n0*FDIM + g];
        float4 vo1 = v_s[(n0+1)*FDIM + g];
        vb[(nb+n0  )*FDIM + g] = make_float4(vo0.x + 0.5f*A[0][0]*au0[0],
                                             vo0.y + 0.5f*A[0][0]*au0[1],
                                             vo0.z + 0.5f*A[0][0]*au0[2], 0.f);
        vb[(nb+n0+1)*FDIM + g] = make_float4(vo1.x + 0.5f*A[0][1]*au1[0],
                                             vo1.y + 0.5f*A[0][1]*au1[1],
                                             vo1.z + 0.5f*A[0][1]*au1[2], 0.f);
    }
}

// ---------------- contraction: 4 CG sites per block, 16-atom chunks (1024 blocks) ----------------
__global__ void __launch_bounds__(128) k_contract(int t, int buf,
    const float* __restrict__ bf,
    const float* __restrict__ xyz, const float* __restrict__ cgxyz,
    const float* __restrict__ assign, float* __restrict__ out)
{
    int f  = threadIdx.x;
    int b  = blockIdx.x >> 4;
    int cg0 = (blockIdx.x & 15) << 2;
    int a0 = blockIdx.y << 4;                 // 16 atoms per chunk, gridDim.y = 32
    const float2* Tc = g_Tcon2 + (size_t)t*PCON*384;
    const float4* vbuf = g_v[buf];
    float cx[4], cy[4], cz[4];
    #pragma unroll
    for (int c = 0; c < 4; c++) {
        int base = (b*NCGC + cg0 + c)*3;
        cx[c] = cgxyz[base]; cy[c] = cgxyz[base+1]; cz[c] = cgxyz[base+2];
    }
    float bf0 = bf[f*3+0], bf1 = bf[f*3+1], bf2 = bf[f*3+2];
    const float inv_step = (PCON-1)/DMAXC;
    float hacc[4], v0a[4], v1a[4], v2a[4];
    #pragma unroll
    for (int c = 0; c < 4; c++) { hacc[c]=0.f; v0a[c]=0.f; v1a[c]=0.f; v2a[c]=0.f; }
    for (int aa = 0; aa < 16; aa++) {
        int n = b*NNODES + a0 + aa;
        float px = xyz[3*n], py = xyz[3*n+1], pz = xyz[3*n+2];
        const float* pp = g_phic + n*384;
        float f0 = pp[f], f1 = pp[128+f], f2 = pp[256+f];
        float4 vp = vbuf[n*FDIM + f];
        const float* as = assign + n*NCGC + cg0;
        #pragma unroll
        for (int c = 0; c < 4; c++) {
            float rx = px - cx[c], ry = py - cy[c], rz = pz - cz[c];
            float d = sqrtf(rx*rx + ry*ry + rz*rz);
            float inv_d = 1.f/d;
            float s = as[c];
            float td = d*inv_step;
            int idx = (int)td;
            float fr;
            if (idx > PCON-2) { idx = PCON-2; fr = 1.f; } else fr = td - idx;
            const float2* ba = Tc + idx*384;
            float2 q0 = ba[f], q1 = ba[128+f], q2 = ba[256+f];
            float w0 = fmaf(fr, q0.y - q0.x, q0.x) + bf0;
            float w1 = fmaf(fr, q1.y - q1.x, q1.x) + bf1;
            float w2 = fmaf(fr, q2.y - q2.x, q2.x) + bf2;
            float x0 = w0*f0, x1 = w1*f1, x2 = w2*f2;
            hacc[c] += s*x1;
            v0a[c]  += s*(x2*(rx*inv_d) + x0*vp.x);
            v1a[c]  += s*(x2*(ry*inv_d) + x0*vp.y);
            v2a[c]  += s*(x2*(rz*inv_d) + x0*vp.z);
        }
    }
    #pragma unroll
    for (int c = 0; c < 4; c++) {
        int cc = b*NCGC + cg0 + c;
        atomicAdd(&out[cc*FDIM + f], hacc[c]);
        float* vout = out + BB*NCGC*FDIM + (cc*FDIM + f)*3;
        atomicAdd(vout+0, v0a[c]);
        atomicAdd(vout+1, v1a[c]);
        atomicAdd(vout+2, v2a[c]);
    }
}

// ---------------- host ----------------
#define MLP_SMEM (204800)
#define UPD_SMEM (225280)

extern "C" void kernel_launch(void* const* d_in, const int* in_sizes, int n_in,
                              void* d_out, int out_size)
{
    const float* h_in   = (const float*)d_in[0];
    const float* H_in   = (const float*)d_in[1];
    const float* xyz    = (const float*)d_in[2];
    const float* cgxyz  = (const float*)d_in[3];
    const float* assign = (const float*)d_in[4];
    const int*   nbr    = (const int*)  d_in[6];
    const float* msgW1  = (const float*)d_in[7];
    const float* msgb1  = (const float*)d_in[8];
    const float* msgW2  = (const float*)d_in[9];
    const float* msgb2  = (const float*)d_in[10];
    const float* We     = (const float*)d_in[11];
    const float* be     = (const float*)d_in[12];
    const float* updU   = (const float*)d_in[13];
    const float* updV   = (const float*)d_in[14];
    const float* updW1  = (const float*)d_in[15];
    const float* updb1  = (const float*)d_in[16];
    const float* updW2  = (const float*)d_in[17];
    const float* updb2  = (const float*)d_in[18];
    const float* conWf  = (const float*)d_in[19];
    const float* conbf  = (const float*)d_in[20];
    const float* conW1  = (const float*)d_in[21];
    const float* conb1  = (const float*)d_in[22];
    const float* conW2  = (const float*)d_in[23];
    const float* conb2  = (const float*)d_in[24];
    float* out = (float*)d_out;

    cudaFuncSetAttribute(k_mlp,    cudaFuncAttributeMaxDynamicSharedMemorySize, MLP_SMEM);
    cudaFuncSetAttribute(k_update, cudaFuncAttributeMaxDynamicSharedMemorySize, UPD_SMEM);

    k_init_geom<<<ETOT/256, 256>>>(h_in, H_in, out, nbr, xyz);          // 1
    k_scan_fill<<<1, BN>>>();                                            // 2
    {
        dim3 gc(PCON/16, NCONVS);
        k_con_table<<<gc, 384>>>(conWf);                                 // 3
    }
    k_mlp<<<BN/8, 512, MLP_SMEM>>>(0, msgW1, msgb1, msgW2, msgb2, 0);    // 4 (profiled)
    {
        dim3 gm(PMSG, NCONVS);
        k_msg_table<<<gm, 128>>>(We, be);                                // 5
    }

    int cur = 0;
    for (int t = 0; t < NCONVS; t++) {
        int nxt = 1 - cur;
        if (t > 0)
            k_mlp<<<BN/8, 512, MLP_SMEM>>>(cur,
                msgW1 + t*FDIM*FDIM, msgb1 + t*FDIM,
                msgW2 + t*FDIM*384,  msgb2 + t*384, 0);
        k_edge<<<BN, 128>>>(t, cur, nxt);
        k_update<<<BN/8, 512, UPD_SMEM>>>(
            updU + t*FDIM*FDIM, updV + t*FDIM*FDIM,
            updW1 + t*2*FDIM*FDIM, updb1 + t*FDIM,
            updW2 + t*FDIM*384,    updb2 + t*384, nxt);
        k_mlp<<<BN/8, 512, MLP_SMEM>>>(nxt,
            conW1 + t*FDIM*FDIM, conb1 + t*FDIM,
            conW2 + t*FDIM*384,  conb2 + t*384, 1);
        dim3 gk(BB*NCGC/4, 32);
        k_contract<<<gk, 128>>>(t, nxt, conbf + t*384, xyz, cgxyz, assign, out);
        cur = nxt;
    }
    (void)in_sizes; (void)n_in; (void)out_size;
}

// round 10
// speedup vs baseline: 1.0758x; 1.0050x over previous
#include <cuda_runtime.h>
#include <math.h>
#include <stdint.h>

#define BB      2
#define NNODES  512
#define NCGC    64
#define FDIM    128
#define NRBF    20
#define NCONVS  3
#define ETOT    32768
#define BN      (BB*NNODES)      // 1024
#define CUT     5.0f
#define PI_F    3.14159265358979323846f
#define PMSG    4096
#define PCON    1024
#define DMAXC   10.0f

// ---------------- persistent device scratch ----------------
__device__ float  g_h[2][BN*FDIM];
__device__ float4 g_v[2][BN*FDIM];
__device__ float4 g_phi4[BN*FDIM];            // (phi_e0, phi_e1, phi_e2, 0) per (node,f)
__device__ float  g_phic[BN*384];
__device__ float4 g_TmsgA[NCONVS*PMSG*FDIM];  // (w0[p], w0[p+1], w1[p], w1[p+1])
__device__ float2 g_TmsgB[NCONVS*PMSG*FDIM];  // (w2[p], w2[p+1])
__device__ float2 g_Tcon2[NCONVS*PCON*384];
__device__ float  g_ed[ETOT];
__device__ float4 g_un[ETOT];
__device__ int    g_pi[ETOT], g_pj[ETOT];
__device__ int    g_ptrn[BN+1];
__device__ int    g_csr[ETOT];

__device__ __forceinline__ float silu(float x) { return x / (1.f + expf(-x)); }

#define CP_COMMIT() asm volatile("cp.async.commit_group;" ::: "memory")
#define CP_WAIT(n)  asm volatile("cp.async.wait_group %0;" :: "n"(n) : "memory")

// ---- packed f32x2 helpers ----
__device__ __forceinline__ uint64_t pack2(float x) {
    uint64_t r; asm("mov.b64 %0, {%1, %1};" : "=l"(r) : "f"(x)); return r;
}
__device__ __forceinline__ uint64_t fma2(uint64_t a, uint64_t b, uint64_t c) {
    uint64_t d; asm("fma.rn.f32x2 %0, %1, %2, %3;" : "=l"(d) : "l"(a), "l"(b), "l"(c)); return d;
}
__device__ __forceinline__ float2 unpack2(uint64_t r) {
    float2 f; asm("mov.b64 {%0, %1}, %2;" : "=f"(f.x), "=f"(f.y) : "l"(r)); return f;
}

// contiguous 64KB (4096 float4) global -> smem via cp.async, 512 threads
__device__ __forceinline__ void stage64(uint32_t sdst, const float4* __restrict__ src, int t)
{
    #pragma unroll
    for (int j = 0; j < 8; j++) {
        int i = t + j*512;
        asm volatile("cp.async.cg.shared.global [%0], [%1], 16;"
                     :: "r"(sdst + i*16), "l"(src + i) : "memory");
    }
}
// W2 chunk mm (128 rows x 128 cols out of 384-col rows) -> smem, 512 threads
__device__ __forceinline__ void stageW2(uint32_t sdst, const float4* __restrict__ W2_4, int mm, int t)
{
    #pragma unroll
    for (int j = 0; j < 8; j++) {
        int i = t + j*512;
        int k = i >> 5, c = i & 31;
        asm volatile("cp.async.cg.shared.global [%0], [%1], 16;"
                     :: "r"(sdst + i*16), "l"(W2_4 + k*96 + mm*32 + c) : "memory");
    }
}

// ---------------- init (h/v/out) + edge geometry, fused ----------------
__global__ void k_init_geom(const float* __restrict__ h_in, const float* __restrict__ H_in,
                            float* __restrict__ out,
                            const int* __restrict__ nbr, const float* __restrict__ xyz)
{
    int idx = blockIdx.x*blockDim.x + threadIdx.x;   // 32768 threads exactly
    {
        int e = idx;
        int b  = nbr[3*e], ii = nbr[3*e+1], jj = nbr[3*e+2];
        int pi = b*NNODES + ii, pj = b*NNODES + jj;
        g_pi[e] = pi; g_pj[e] = pj;
        float rx = xyz[3*pi]   - xyz[3*pj];
        float ry = xyz[3*pi+1] - xyz[3*pj+1];
        float rz = xyz[3*pi+2] - xyz[3*pj+2];
        float d = sqrtf(rx*rx + ry*ry + rz*rz);
        g_ed[e] = d;
        float inv = 1.f/d;
        g_un[e] = make_float4(rx*inv, ry*inv, rz*inv, 0.f);
    }
    for (int i = idx; i < BN*FDIM; i += ETOT) {
        g_h[0][i] = h_in[i];
        g_v[0][i] = make_float4(0.f,0.f,0.f,0.f);
    }
    for (int i = idx; i < BB*NCGC*FDIM*4; i += ETOT)
        out[i] = (i < BB*NCGC*FDIM) ? H_in[i] : 0.f;
}

// ---------------- count + scan + CSR fill, one block, smem counters ----------------
__global__ void k_scan_fill()
{
    __shared__ int s_cnt[BN];
    __shared__ int s_scan[BN];
    __shared__ int s_fill[BN];
    int t = threadIdx.x;   // 1024
    s_cnt[t] = 0;
    __syncthreads();
    for (int e = t; e < ETOT; e += BN)
        if (g_ed[e] < CUT) atomicAdd(&s_cnt[g_pi[e]], 1);
    __syncthreads();
    s_scan[t] = s_cnt[t];
    __syncthreads();
    for (int off = 1; off < BN; off <<= 1) {
        int x = (t >= off) ? s_scan[t-off] : 0;
        __syncthreads();
        s_scan[t] += x;
        __syncthreads();
    }
    g_ptrn[t+1] = s_scan[t];
    if (t == 0) g_ptrn[0] = 0;
    s_cnt[t] = s_scan[t] - s_cnt[t];
    s_fill[t] = 0;
    __syncthreads();
    for (int e = t; e < ETOT; e += BN) {
        if (g_ed[e] < CUT) {
            int pi = g_pi[e];
            int pos = s_cnt[pi] + atomicAdd(&s_fill[pi], 1);
            g_csr[pos] = e;
        }
    }
}

// ---------------- message table (pair-packed float4/float2, f-indexed) ----------------
__global__ void k_msg_table(const float* __restrict__ We, const float* __restrict__ be)
{
    int p = blockIdx.x, t = blockIdx.y, f = threadIdx.x; // 128 threads
    const float step = CUT/(PMSG-1);
    float d0 = p*step;
    int p1i = (p+1 < PMSG) ? p+1 : PMSG-1;
    float d1 = p1i*step;
    float env0 = (d0 < CUT) ? 0.5f*(cosf(PI_F*d0/CUT) + 1.f) : 0.f;
    float env1 = (d1 < CUT) ? 0.5f*(cosf(PI_F*d1/CUT) + 1.f) : 0.f;
    __shared__ float rb[2][NRBF];
    if (f < 2*NRBF) {
        int which = f/NRBF, k = f%NRBF;
        float d = which ? d1 : d0;
        float dd = fmaxf(d, 1e-6f);
        rb[which][k] = sinf((k+1)*PI_F/CUT*dd)/dd;
    }
    __syncthreads();
    const float* Wt = We + t*NRBF*384;
    const float* bt = be + t*384;
    float b0 = bt[f], b1 = bt[128+f], b2 = bt[256+f];
    float w0p0=b0, w0p1=b0, w1p0=b1, w1p1=b1, w2p0=b2, w2p1=b2;
    #pragma unroll
    for (int k = 0; k < NRBF; k++) {
        float wa = Wt[k*384+f], wb = Wt[k*384+128+f], wc = Wt[k*384+256+f];
        float r0 = rb[0][k], r1 = rb[1][k];
        w0p0 += r0*wa; w0p1 += r1*wa;
        w1p0 += r0*wb; w1p1 += r1*wb;
        w2p0 += r0*wc; w2p1 += r1*wc;
    }
    int o = (t*PMSG+p)*FDIM + f;
    g_TmsgA[o] = make_float4(w0p0*env0, w0p1*env1, w1p0*env0, w1p1*env1);
    g_TmsgB[o] = make_float2(w2p0*env0, w2p1*env1);
}

// ---------------- contraction table (pair-packed, columns remapped to [e3][f]) ----------------
__global__ void k_con_table(const float* __restrict__ Wf)
{
    __shared__ float es[17][FDIM];
    int tid = threadIdx.x;              // 384 threads
    int p0  = blockIdx.x*16, t = blockIdx.y;
    const float step = DMAXC/(PCON-1);
    for (int i = tid; i < 17*FDIM; i += 384) {
        int pl = i / FDIM, k = i % FDIM;
        float d = (p0+pl)*step;
        float o = CUT*k/127.f;
        float x = d - o;
        es[pl][k] = expf(-x*x);
    }
    __syncthreads();
    int src = (tid & 127)*3 + (tid >> 7);
    float acc[17];
    #pragma unroll
    for (int p = 0; p < 17; p++) acc[p] = 0.f;
    const float* Wt = Wf + t*FDIM*384;
    for (int k = 0; k < FDIM; k++) {
        float w = Wt[k*384 + src];
        #pragma unroll
        for (int p = 0; p < 17; p++) acc[p] += es[p][k]*w;
    }
    #pragma unroll
    for (int p = 0; p < 16; p++)
        g_Tcon2[(t*PCON + p0 + p)*384 + tid] = make_float2(acc[p], acc[p+1]);
}

// ---------------- fused 2-layer MLP, cp.async triple-buffered, f32x2 math ----------------
// thread = (node n = t>>6, g-pair gp = (t&63)*2)
// smem floats: wsW1[16384] | bufA[16384] | bufB[16384] | h_s[1024] | hid_s[1024] = 204800 B
__global__ void __launch_bounds__(512) k_mlp(int hsel,
                      const float* __restrict__ W1, const float* __restrict__ b1,
                      const float* __restrict__ W2, const float* __restrict__ b2, int dst_sel)
{
    extern __shared__ float sm[];
    uint32_t smb = (uint32_t)__cvta_generic_to_shared(sm);
    float* wsW1  = sm;
    float* bufA  = sm + 16384;
    float* bufB  = sm + 32768;
    float* h_s   = sm + 49152;
    float* hid_s = sm + 50176;
    int t = threadIdx.x;                // 512
    int nb = blockIdx.x*8;
    const float4* W2_4 = (const float4*)W2;

    stage64(smb,            (const float4*)W1, t); CP_COMMIT();   // g0 -> wsW1
    stageW2(smb + 16384*4,  W2_4, 0, t);           CP_COMMIT();   // g1 -> bufA
    stageW2(smb + 32768*4,  W2_4, 1, t);           CP_COMMIT();   // g2 -> bufB
    const float* hb = g_h[hsel];
    for (int i = t; i < 8*FDIM; i += 512)
        h_s[i] = hb[nb*FDIM + i];

    CP_WAIT(2);
    __syncthreads();                     // W1 + h ready
    int n  = t >> 6;            // 0..7
    int gp = (t & 63) << 1;     // 0..126 even
    {
        uint64_t acc = *(const uint64_t*)&b1[gp];
        #pragma unroll 8
        for (int f = 0; f < FDIM; f += 4) {
            float4 hv = *(const float4*)&h_s[n*FDIM + f];
            acc = fma2(pack2(hv.x), *(const uint64_t*)&wsW1[(f  )*FDIM+gp], acc);
            acc = fma2(pack2(hv.y), *(const uint64_t*)&wsW1[(f+1)*FDIM+gp], acc);
            acc = fma2(pack2(hv.z), *(const uint64_t*)&wsW1[(f+2)*FDIM+gp], acc);
            acc = fma2(pack2(hv.w), *(const uint64_t*)&wsW1[(f+3)*FDIM+gp], acc);
        }
        float2 hu = unpack2(acc);
        *(float2*)&hid_s[n*FDIM + gp] = make_float2(silu(hu.x), silu(hu.y));
    }
    uint64_t A[3];
    CP_WAIT(1);
    __syncthreads();                     // hid visible + bufA(c0) ready
    {   // chunk0 from bufA
        uint64_t acc = *(const uint64_t*)&b2[gp];
        #pragma unroll 8
        for (int k = 0; k < FDIM; k += 4) {
            float4 hv = *(const float4*)&hid_s[n*FDIM + k];
            acc = fma2(pack2(hv.x), *(const uint64_t*)&bufA[(k  )*FDIM+gp], acc);
            acc = fma2(pack2(hv.y), *(const uint64_t*)&bufA[(k+1)*FDIM+gp], acc);
            acc = fma2(pack2(hv.z), *(const uint64_t*)&bufA[(k+2)*FDIM+gp], acc);
            acc = fma2(pack2(hv.w), *(const uint64_t*)&bufA[(k+3)*FDIM+gp], acc);
        }
        A[0] = acc;
    }
    __syncthreads();                     // all done reading bufA
    stageW2(smb + 16384*4, W2_4, 2, t); CP_COMMIT();   // g3 -> bufA
    CP_WAIT(1);
    __syncthreads();                     // bufB(c1) ready
    {   // chunk1 from bufB
        uint64_t acc = *(const uint64_t*)&b2[128+gp];
        #pragma unroll 8
        for (int k = 0; k < FDIM; k += 4) {
            float4 hv = *(const float4*)&hid_s[n*FDIM + k];
            acc = fma2(pack2(hv.x), *(const uint64_t*)&bufB[(k  )*FDIM+gp], acc);
            acc = fma2(pack2(hv.y), *(const uint64_t*)&bufB[(k+1)*FDIM+gp], acc);
            acc = fma2(pack2(hv.z), *(const uint64_t*)&bufB[(k+2)*FDIM+gp], acc);
            acc = fma2(pack2(hv.w), *(const uint64_t*)&bufB[(k+3)*FDIM+gp], acc);
        }
        A[1] = acc;
    }
    CP_WAIT(0);
    __syncthreads();                     // bufA(c2) ready
    {   // chunk2 from bufA
        uint64_t acc = *(const uint64_t*)&b2[256+gp];
        #pragma unroll 8
        for (int k = 0; k < FDIM; k += 4) {
            float4 hv = *(const float4*)&hid_s[n*FDIM + k];
            acc = fma2(pack2(hv.x), *(const uint64_t*)&bufA[(k  )*FDIM+gp], acc);
            acc = fma2(pack2(hv.y), *(const uint64_t*)&bufA[(k+1)*FDIM+gp], acc);
            acc = fma2(pack2(hv.z), *(const uint64_t*)&bufA[(k+2)*FDIM+gp], acc);
            acc = fma2(pack2(hv.w), *(const uint64_t*)&bufA[(k+3)*FDIM+gp], acc);
        }
        A[2] = acc;
    }
    float2 a0 = unpack2(A[0]), a1 = unpack2(A[1]), a2 = unpack2(A[2]);
    if (dst_sel == 0) {
        g_phi4[(nb+n)*FDIM + gp]   = make_float4(a0.x, a1.x, a2.x, 0.f);
        g_phi4[(nb+n)*FDIM + gp+1] = make_float4(a0.y, a1.y, a2.y, 0.f);
    } else {
        #pragma unroll
        for (int mm = 0; mm < 3; mm++) {
            float2 av = (mm == 0) ? a0 : (mm == 1) ? a1 : a2;
            int m0 = mm*128 + gp;
            int o0 = ((m0 % 3) << 7) + (m0 / 3);
            int m1 = m0 + 1;
            int o1 = ((m1 % 3) << 7) + (m1 / 3);
            g_phic[(nb+n)*384 + o0] = av.x;
            g_phic[(nb+n)*384 + o1] = av.y;
        }
    }
}

// ---------------- edge message pass: packed table + phi4 ----------------
__global__ void __launch_bounds__(128) k_edge(int t, int cur, int nxt)
{
    int i = blockIdx.x, f = threadIdx.x;
    int e0 = g_ptrn[i], e1 = g_ptrn[i+1];
    const float4* TA = g_TmsgA + (size_t)t*PMSG*FDIM;
    const float2* TB = g_TmsgB + (size_t)t*PMSG*FDIM;
    const float4* vcur = g_v[cur];
    const float inv_step = (PMSG-1)/CUT;
    float acch = 0.f, av0 = 0.f, av1 = 0.f, av2 = 0.f;
    for (int q = e0; q < e1; q++) {
        int e = g_csr[q];
        float d = g_ed[e];
        float u = d*inv_step;
        int idx = (int)u; if (idx > PMSG-2) idx = PMSG-2;
        float fr = u - idx;
        float4 Aq = TA[idx*FDIM + f];
        float2 Bq = TB[idx*FDIM + f];
        float w0 = fmaf(fr, Aq.y - Aq.x, Aq.x);
        float w1 = fmaf(fr, Aq.w - Aq.z, Aq.z);
        float w2 = fmaf(fr, Bq.y - Bq.x, Bq.x);
        int pj = g_pj[e];
        float4 ph = g_phi4[pj*FDIM + f];
        float i0 = ph.x*w0, i1 = ph.y*w1, i2 = ph.z*w2;
        float4 uq = g_un[e];
        float4 vj = vcur[pj*FDIM + f];
        acch += i1;
        av0  += i2*uq.x + i0*vj.x;
        av1  += i2*uq.y + i0*vj.y;
        av2  += i2*uq.z + i0*vj.z;
    }
    g_h[nxt][i*FDIM+f] = g_h[cur][i*FDIM+f] + 0.5f*acch;
    float4 vc = vcur[i*FDIM+f];
    g_v[nxt][i*FDIM+f] = make_float4(vc.x + 0.5f*av0, vc.y + 0.5f*av1, vc.z + 0.5f*av2, 0.f);
}

// ---------------- node update: cp.async 3-buffer rotation, fused U+V phase ----------------
// smem floats: B0[16384] | B1[16384] | B2[16384] | h_s[1024] | v_s[4096] | vn_s[1024] | hid_s[1024]
//            = 56320 floats = 225280 B
__global__ void __launch_bounds__(512) k_update(const float* __restrict__ U, const float* __restrict__ Vm,
                         const float* __restrict__ W1, const float* __restrict__ b1,
                         const float* __restrict__ W2, const float* __restrict__ b2, int buf)
{
    extern __shared__ float sm[];
    uint32_t smb = (uint32_t)__cvta_generic_to_shared(sm);
    float*  B0    = sm;
    float*  B1    = sm + 16384;
    float*  B2    = sm + 32768;
    float*  h_s   = sm + 49152;
    float4* v_s   = (float4*)(sm + 50176);
    float*  vn_s  = sm + 54272;
    float*  hid_s = sm + 55296;
    int t = threadIdx.x;                // 512
    int g = t & 127, n0 = (t >> 7) * 2;
    int nb = blockIdx.x*8;
    float*  hb = g_h[buf];
    float4* vb = g_v[buf];
    const float4* W2_4 = (const float4*)W2;

    stage64(smb,           (const float4*)U,  t); CP_COMMIT();   // g0 -> B0 (U)
    stage64(smb + 16384*4, (const float4*)Vm, t); CP_COMMIT();   // g1 -> B1 (V)
    stage64(smb + 32768*4, (const float4*)W1, t); CP_COMMIT();   // g2 -> B2 (W1a)
    for (int i = t; i < 8*FDIM; i += 512) {
        h_s[i] = hb[nb*FDIM + i];
        v_s[i] = vb[nb*FDIM + i];
    }

    CP_WAIT(1);
    __syncthreads();                     // B0=U, B1=V, h/v ready
    float au0[3] = {0.f,0.f,0.f}, au1[3] = {0.f,0.f,0.f};
    float av0[3] = {0.f,0.f,0.f}, av1[3] = {0.f,0.f,0.f};
    #pragma unroll 4
    for (int f = 0; f < FDIM; f++) {
        float uu = B0[f*FDIM+g];
        float vv = B1[f*FDIM+g];
        float4 x0 = v_s[n0*FDIM + f];
        float4 x1 = v_s[(n0+1)*FDIM + f];
        au0[0] += x0.x*uu; au0[1] += x0.y*uu; au0[2] += x0.z*uu;
        au1[0] += x1.x*uu; au1[1] += x1.y*uu; au1[2] += x1.z*uu;
        av0[0] += x0.x*vv; av0[1] += x0.y*vv; av0[2] += x0.z*vv;
        av1[0] += x1.x*vv; av1[1] += x1.y*vv; av1[2] += x1.z*vv;
    }
    float dot0 = au0[0]*av0[0] + au0[1]*av0[1] + au0[2]*av0[2];
    float dot1 = au1[0]*av1[0] + au1[1]*av1[1] + au1[2]*av1[2];
    vn_s[n0*FDIM + g]     = sqrtf(av0[0]*av0[0] + av0[1]*av0[1] + av0[2]*av0[2] + 1e-15f);
    vn_s[(n0+1)*FDIM + g] = sqrtf(av1[0]*av1[0] + av1[1]*av1[1] + av1[2]*av1[2] + 1e-15f);
    __syncthreads();                     // done reading B0, B1
    stage64(smb, ((const float4*)W1) + 4096, t); CP_COMMIT();    // g3 -> B0 (W1b)
    stageW2(smb + 16384*4, W2_4, 0, t);          CP_COMMIT();    // g4 -> B1 (W2c0)
    CP_WAIT(2);
    __syncthreads();                     // B2=W1a ready
    float ac0 = b1[g], ac1 = ac0;
    #pragma unroll 8
    for (int f = 0; f < FDIM; f += 4) {
        float4 h0 = *(const float4*)&h_s[n0*FDIM + f];
        float4 h1 = *(const float4*)&h_s[(n0+1)*FDIM + f];
        float w0 = B2[f*FDIM+g], w1 = B2[(f+1)*FDIM+g];
        float w2 = B2[(f+2)*FDIM+g], w3 = B2[(f+3)*FDIM+g];
        ac0 += h0.x*w0 + h0.y*w1 + h0.z*w2 + h0.w*w3;
        ac1 += h1.x*w0 + h1.y*w1 + h1.z*w2 + h1.w*w3;
    }
    __syncthreads();                     // done reading B2
    stageW2(smb + 32768*4, W2_4, 1, t); CP_COMMIT();             // g5 -> B2 (W2c1)
    CP_WAIT(2);
    __syncthreads();                     // B0=W1b ready, vn visible
    #pragma unroll 8
    for (int f = 0; f < FDIM; f += 4) {
        float4 h0 = *(const float4*)&vn_s[n0*FDIM + f];
        float4 h1 = *(const float4*)&vn_s[(n0+1)*FDIM + f];
        float w0 = B0[f*FDIM+g], w1 = B0[(f+1)*FDIM+g];
        float w2 = B0[(f+2)*FDIM+g], w3 = B0[(f+3)*FDIM+g];
        ac0 += h0.x*w0 + h0.y*w1 + h0.z*w2 + h0.w*w3;
        ac1 += h1.x*w0 + h1.y*w1 + h1.z*w2 + h1.w*w3;
    }
    hid_s[n0*FDIM+g]     = silu(ac0);
    hid_s[(n0+1)*FDIM+g] = silu(ac1);
    __syncthreads();                     // done reading B0
    stageW2(smb, W2_4, 2, t); CP_COMMIT();                       // g6 -> B0 (W2c2)
    float A[3][2];
    CP_WAIT(2);
    __syncthreads();                     // B1=W2c0 ready, hid visible
    {
        float b = b2[g];
        float a0 = b, a1 = b;
        #pragma unroll 8
        for (int k = 0; k < FDIM; k += 4) {
            float4 h0 = *(const float4*)&hid_s[n0*FDIM + k];
            float4 h1 = *(const float4*)&hid_s[(n0+1)*FDIM + k];
            float w0 = B1[k*FDIM+g], w1 = B1[(k+1)*FDIM+g];
            float w2 = B1[(k+2)*FDIM+g], w3 = B1[(k+3)*FDIM+g];
            a0 += h0.x*w0 + h0.y*w1 + h0.z*w2 + h0.w*w3;
            a1 += h1.x*w0 + h1.y*w1 + h1.z*w2 + h1.w*w3;
        }
        A[0][0] = a0; A[0][1] = a1;
    }
    CP_WAIT(1);
    __syncthreads();                     // B2=W2c1 ready
    {
        float b = b2[128+g];
        float a0 = b, a1 = b;
        #pragma unroll 8
        for (int k = 0; k < FDIM; k += 4) {
            float4 h0 = *(const float4*)&hid_s[n0*FDIM + k];
            float4 h1 = *(const float4*)&hid_s[(n0+1)*FDIM + k];
            float w0 = B2[k*FDIM+g], w1 = B2[(k+1)*FDIM+g];
            float w2 = B2[(k+2)*FDIM+g], w3 = B2[(k+3)*FDIM+g];
            a0 += h0.x*w0 + h0.y*w1 + h0.z*w2 + h0.w*w3;
            a1 += h1.x*w0 + h1.y*w1 + h1.z*w2 + h1.w*w3;
        }
        A[1][0] = a0; A[1][1] = a1;
    }
    CP_WAIT(0);
    __syncthreads();                     // B0=W2c2 ready
    {
        float b = b2[256+g];
        float a0 = b, a1 = b;
        #pragma unroll 8
        for (int k = 0; k < FDIM; k += 4) {
            float4 h0 = *(const float4*)&hid_s[n0*FDIM + k];
            float4 h1 = *(const float4*)&hid_s[(n0+1)*FDIM + k];
            float w0 = B0[k*FDIM+g], w1 = B0[(k+1)*FDIM+g];
            float w2 = B0[(k+2)*FDIM+g], w3 = B0[(k+3)*FDIM+g];
            a0 += h0.x*w0 + h0.y*w1 + h0.z*w2 + h0.w*w3;
            a1 += h1.x*w0 + h1.y*w1 + h1.z*w2 + h1.w*w3;
        }
        A[2][0] = a0; A[2][1] = a1;
    }
    {
        float ds0 = dot0*A[1][0] + A[2][0];
        float ds1 = dot1*A[1][1] + A[2][1];
        hb[(nb+n0  )*FDIM + g] = h_s[n0*FDIM+g]     + 0.5f*ds0;
        hb[(nb+n0+1)*FDIM + g] = h_s[(n0+1)*FDIM+g] + 0.5f*ds1;
        float4 vo0 = v_s[n0*FDIM + g];
        float4 vo1 = v_s[(n0+1)*FDIM + g];
        vb[(nb+n0  )*FDIM + g] = make_float4(vo0.x + 0.5f*A[0][0]*au0[0],
                                             vo0.y + 0.5f*A[0][0]*au0[1],
                                             vo0.z + 0.5f*A[0][0]*au0[2], 0.f);
        vb[(nb+n0+1)*FDIM + g] = make_float4(vo1.x + 0.5f*A[0][1]*au1[0],
                                             vo1.y + 0.5f*A[0][1]*au1[1],
                                             vo1.z + 0.5f*A[0][1]*au1[2], 0.f);
    }
}

// ---------------- contraction: 4 CG sites per block, 16-atom chunks (1024 blocks) ----------------
__global__ void __launch_bounds__(128) k_contract(int t, int buf,
    const float* __restrict__ bf,
    const float* __restrict__ xyz, const float* __restrict__ cgxyz,
    const float* __restrict__ assign, float* __restrict__ out)
{
    int f  = threadIdx.x;
    int b  = blockIdx.x >> 4;
    int cg0 = (blockIdx.x & 15) << 2;
    int a0 = blockIdx.y << 4;                 // 16 atoms per chunk, gridDim.y = 32
    const float2* Tc = g_Tcon2 + (size_t)t*PCON*384;
    const float4* vbuf = g_v[buf];
    float cx[4], cy[4], cz[4];
    #pragma unroll
    for (int c = 0; c < 4; c++) {
        int base = (b*NCGC + cg0 + c)*3;
        cx[c] = cgxyz[base]; cy[c] = cgxyz[base+1]; cz[c] = cgxyz[base+2];
    }
    float bf0 = bf[f*3+0], bf1 = bf[f*3+1], bf2 = bf[f*3+2];
    const float inv_step = (PCON-1)/DMAXC;
    float hacc[4], v0a[4], v1a[4], v2a[4];
    #pragma unroll
    for (int c = 0; c < 4; c++) { hacc[c]=0.f; v0a[c]=0.f; v1a[c]=0.f; v2a[c]=0.f; }
    for (int aa = 0; aa < 16; aa++) {
        int n = b*NNODES + a0 + aa;
        float px = xyz[3*n], py = xyz[3*n+1], pz = xyz[3*n+2];
        const float* pp = g_phic + n*384;
        float f0 = pp[f], f1 = pp[128+f], f2 = pp[256+f];
        float4 vp = vbuf[n*FDIM + f];
        const float* as = assign + n*NCGC + cg0;
        #pragma unroll
        for (int c = 0; c < 4; c++) {
            float rx = px - cx[c], ry = py - cy[c], rz = pz - cz[c];
            float d = sqrtf(rx*rx + ry*ry + rz*rz);
            float inv_d = 1.f/d;
            float s = as[c];
            float td = d*inv_step;
            int idx = (int)td;
            float fr;
            if (idx > PCON-2) { idx = PCON-2; fr = 1.f; } else fr = td - idx;
            const float2* ba = Tc + idx*384;
            float2 q0 = ba[f], q1 = ba[128+f], q2 = ba[256+f];
            float w0 = fmaf(fr, q0.y - q0.x, q0.x) + bf0;
            float w1 = fmaf(fr, q1.y - q1.x, q1.x) + bf1;
            float w2 = fmaf(fr, q2.y - q2.x, q2.x) + bf2;
            float x0 = w0*f0, x1 = w1*f1, x2 = w2*f2;
            hacc[c] += s*x1;
            v0a[c]  += s*(x2*(rx*inv_d) + x0*vp.x);
            v1a[c]  += s*(x2*(ry*inv_d) + x0*vp.y);
            v2a[c]  += s*(x2*(rz*inv_d) + x0*vp.z);
        }
    }
    #pragma unroll
    for (int c = 0; c < 4; c++) {
        int cc = b*NCGC + cg0 + c;
        atomicAdd(&out[cc*FDIM + f], hacc[c]);
        float* vout = out + BB*NCGC*FDIM + (cc*FDIM + f)*3;
        atomicAdd(vout+0, v0a[c]);
        atomicAdd(vout+1, v1a[c]);
        atomicAdd(vout+2, v2a[c]);
    }
}

// ---------------- host ----------------
#define MLP_SMEM (204800)
#define UPD_SMEM (225280)

extern "C" void kernel_launch(void* const* d_in, const int* in_sizes, int n_in,
                              void* d_out, int out_size)
{
    const float* h_in   = (const float*)d_in[0];
    const float* H_in   = (const float*)d_in[1];
    const float* xyz    = (const float*)d_in[2];
    const float* cgxyz  = (const float*)d_in[3];
    const float* assign = (const float*)d_in[4];
    const int*   nbr    = (const int*)  d_in[6];
    const float* msgW1  = (const float*)d_in[7];
    const float* msgb1  = (const float*)d_in[8];
    const float* msgW2  = (const float*)d_in[9];
    const float* msgb2  = (const float*)d_in[10];
    const float* We     = (const float*)d_in[11];
    const float* be     = (const float*)d_in[12];
    const float* updU   = (const float*)d_in[13];
    const float* updV   = (const float*)d_in[14];
    const float* updW1  = (const float*)d_in[15];
    const float* updb1  = (const float*)d_in[16];
    const float* updW2  = (const float*)d_in[17];
    const float* updb2  = (const float*)d_in[18];
    const float* conWf  = (const float*)d_in[19];
    const float* conbf  = (const float*)d_in[20];
    const float* conW1  = (const float*)d_in[21];
    const float* conb1  = (const float*)d_in[22];
    const float* conW2  = (const float*)d_in[23];
    const float* conb2  = (const float*)d_in[24];
    float* out = (float*)d_out;

    cudaFuncSetAttribute(k_mlp,    cudaFuncAttributeMaxDynamicSharedMemorySize, MLP_SMEM);
    cudaFuncSetAttribute(k_update, cudaFuncAttributeMaxDynamicSharedMemorySize, UPD_SMEM);

    k_init_geom<<<ETOT/256, 256>>>(h_in, H_in, out, nbr, xyz);          // 1
    k_scan_fill<<<1, BN>>>();                                            // 2
    {
        dim3 gc(PCON/16, NCONVS);
        k_con_table<<<gc, 384>>>(conWf);                                 // 3
    }
    k_mlp<<<BN/8, 512, MLP_SMEM>>>(0, msgW1, msgb1, msgW2, msgb2, 0);    // 4 (profiled)
    {
        dim3 gm(PMSG, NCONVS);
        k_msg_table<<<gm, 128>>>(We, be);                                // 5
    }

    int cur = 0;
    for (int t = 0; t < NCONVS; t++) {
        int nxt = 1 - cur;
        if (t > 0)
            k_mlp<<<BN/8, 512, MLP_SMEM>>>(cur,
                msgW1 + t*FDIM*FDIM, msgb1 + t*FDIM,
                msgW2 + t*FDIM*384,  msgb2 + t*384, 0);
        k_edge<<<BN, 128>>>(t, cur, nxt);
        k_update<<<BN/8, 512, UPD_SMEM>>>(
            updU + t*FDIM*FDIM, updV + t*FDIM*FDIM,
            updW1 + t*2*FDIM*FDIM, updb1 + t*FDIM,
            updW2 + t*FDIM*384,    updb2 + t*384, nxt);
        k_mlp<<<BN/8, 512, MLP_SMEM>>>(nxt,
            conW1 + t*FDIM*FDIM, conb1 + t*FDIM,
            conW2 + t*FDIM*384,  conb2 + t*384, 1);
        dim3 gk(BB*NCGC/4, 32);
        k_contract<<<gk, 128>>>(t, nxt, conbf + t*384, xyz, cgxyz, assign, out);
        cur = nxt;
    }
    (void)in_sizes; (void)n_in; (void)out_size;
}

// round 11
// speedup vs baseline: 1.1022x; 1.0246x over previous
#include <cuda_runtime.h>
#include <math.h>
#include <stdint.h>

#define BB      2
#define NNODES  512
#define NCGC    64
#define FDIM    128
#define NRBF    20
#define NCONVS  3
#define ETOT    32768
#define BN      (BB*NNODES)      // 1024
#define CUT     5.0f
#define PI_F    3.14159265358979323846f
#define PMSG    4096
#define PCON    1024
#define DMAXC   10.0f

// ---------------- persistent device scratch ----------------
__device__ float  g_h[2][BN*FDIM];
__device__ float4 g_v[2][BN*FDIM];
__device__ float4 g_phi4[BN*FDIM];            // (phi_e0, phi_e1, phi_e2, 0) per (node,f)
__device__ float  g_phic[BN*384];
__device__ float4 g_TmsgA[NCONVS*PMSG*FDIM];  // (w0[p], w0[p+1], w1[p], w1[p+1])
__device__ float2 g_TmsgB[NCONVS*PMSG*FDIM];  // (w2[p], w2[p+1])
__device__ float2 g_Tcon2[NCONVS*PCON*384];
__device__ float  g_ed[ETOT];
__device__ float4 g_un[ETOT];
__device__ int    g_pi[ETOT], g_pj[ETOT];
__device__ int    g_ptrn[BN+1];
__device__ int    g_csr[ETOT];

__device__ __forceinline__ float silu(float x) { return x / (1.f + expf(-x)); }

#define CP_COMMIT() asm volatile("cp.async.commit_group;" ::: "memory")
#define CP_WAIT(n)  asm volatile("cp.async.wait_group %0;" :: "n"(n) : "memory")

// contiguous 64KB (4096 float4) global -> smem via cp.async, 512 threads
__device__ __forceinline__ void stage64(uint32_t sdst, const float4* __restrict__ src, int t)
{
    #pragma unroll
    for (int j = 0; j < 8; j++) {
        int i = t + j*512;
        asm volatile("cp.async.cg.shared.global [%0], [%1], 16;"
                     :: "r"(sdst + i*16), "l"(src + i) : "memory");
    }
}
// W2 chunk mm (128 rows x 128 cols out of 384-col rows) -> smem, 512 threads
__device__ __forceinline__ void stageW2(uint32_t sdst, const float4* __restrict__ W2_4, int mm, int t)
{
    #pragma unroll
    for (int j = 0; j < 8; j++) {
        int i = t + j*512;
        int k = i >> 5, c = i & 31;
        asm volatile("cp.async.cg.shared.global [%0], [%1], 16;"
                     :: "r"(sdst + i*16), "l"(W2_4 + k*96 + mm*32 + c) : "memory");
    }
}

// GEMV pair: out column g for nodes n0, n0+1, weights in BUF (128x128 col-major-ish), input IN
#define GEMV2(BUF, IN, a0, a1) \
    _Pragma("unroll 8") \
    for (int k_ = 0; k_ < FDIM; k_ += 4) { \
        float4 h0_ = *(const float4*)&IN[n0*FDIM + k_]; \
        float4 h1_ = *(const float4*)&IN[(n0+1)*FDIM + k_]; \
        float w0_ = BUF[k_*FDIM+g], w1_ = BUF[(k_+1)*FDIM+g]; \
        float w2_ = BUF[(k_+2)*FDIM+g], w3_ = BUF[(k_+3)*FDIM+g]; \
        a0 += h0_.x*w0_ + h0_.y*w1_ + h0_.z*w2_ + h0_.w*w3_; \
        a1 += h1_.x*w0_ + h1_.y*w1_ + h1_.z*w2_ + h1_.w*w3_; \
    }

// ---------------- init (h/v/out) + edge geometry, fused ----------------
__global__ void k_init_geom(const float* __restrict__ h_in, const float* __restrict__ H_in,
                            float* __restrict__ out,
                            const int* __restrict__ nbr, const float* __restrict__ xyz)
{
    int idx = blockIdx.x*blockDim.x + threadIdx.x;   // 32768 threads exactly
    {
        int e = idx;
        int b  = nbr[3*e], ii = nbr[3*e+1], jj = nbr[3*e+2];
        int pi = b*NNODES + ii, pj = b*NNODES + jj;
        g_pi[e] = pi; g_pj[e] = pj;
        float rx = xyz[3*pi]   - xyz[3*pj];
        float ry = xyz[3*pi+1] - xyz[3*pj+1];
        float rz = xyz[3*pi+2] - xyz[3*pj+2];
        float d = sqrtf(rx*rx + ry*ry + rz*rz);
        g_ed[e] = d;
        float inv = 1.f/d;
        g_un[e] = make_float4(rx*inv, ry*inv, rz*inv, 0.f);
    }
    for (int i = idx; i < BN*FDIM; i += ETOT) {
        g_h[0][i] = h_in[i];
        g_v[0][i] = make_float4(0.f,0.f,0.f,0.f);
    }
    for (int i = idx; i < BB*NCGC*FDIM*4; i += ETOT)
        out[i] = (i < BB*NCGC*FDIM) ? H_in[i] : 0.f;
}

// ---------------- count + scan + CSR fill, one block, smem counters ----------------
__global__ void k_scan_fill()
{
    __shared__ int s_cnt[BN];
    __shared__ int s_scan[BN];
    __shared__ int s_fill[BN];
    int t = threadIdx.x;   // 1024
    s_cnt[t] = 0;
    __syncthreads();
    for (int e = t; e < ETOT; e += BN)
        if (g_ed[e] < CUT) atomicAdd(&s_cnt[g_pi[e]], 1);
    __syncthreads();
    s_scan[t] = s_cnt[t];
    __syncthreads();
    for (int off = 1; off < BN; off <<= 1) {
        int x = (t >= off) ? s_scan[t-off] : 0;
        __syncthreads();
        s_scan[t] += x;
        __syncthreads();
    }
    g_ptrn[t+1] = s_scan[t];
    if (t == 0) g_ptrn[0] = 0;
    s_cnt[t] = s_scan[t] - s_cnt[t];
    s_fill[t] = 0;
    __syncthreads();
    for (int e = t; e < ETOT; e += BN) {
        if (g_ed[e] < CUT) {
            int pi = g_pi[e];
            int pos = s_cnt[pi] + atomicAdd(&s_fill[pi], 1);
            g_csr[pos] = e;
        }
    }
}

// ---------------- message table (pair-packed float4/float2, f-indexed) ----------------
__global__ void k_msg_table(const float* __restrict__ We, const float* __restrict__ be)
{
    int p = blockIdx.x, t = blockIdx.y, f = threadIdx.x; // 128 threads
    const float step = CUT/(PMSG-1);
    float d0 = p*step;
    int p1i = (p+1 < PMSG) ? p+1 : PMSG-1;
    float d1 = p1i*step;
    float env0 = (d0 < CUT) ? 0.5f*(cosf(PI_F*d0/CUT) + 1.f) : 0.f;
    float env1 = (d1 < CUT) ? 0.5f*(cosf(PI_F*d1/CUT) + 1.f) : 0.f;
    __shared__ float rb[2][NRBF];
    if (f < 2*NRBF) {
        int which = f/NRBF, k = f%NRBF;
        float d = which ? d1 : d0;
        float dd = fmaxf(d, 1e-6f);
        rb[which][k] = sinf((k+1)*PI_F/CUT*dd)/dd;
    }
    __syncthreads();
    const float* Wt = We + t*NRBF*384;
    const float* bt = be + t*384;
    float b0 = bt[f], b1 = bt[128+f], b2 = bt[256+f];
    float w0p0=b0, w0p1=b0, w1p0=b1, w1p1=b1, w2p0=b2, w2p1=b2;
    #pragma unroll
    for (int k = 0; k < NRBF; k++) {
        float wa = Wt[k*384+f], wb = Wt[k*384+128+f], wc = Wt[k*384+256+f];
        float r0 = rb[0][k], r1 = rb[1][k];
        w0p0 += r0*wa; w0p1 += r1*wa;
        w1p0 += r0*wb; w1p1 += r1*wb;
        w2p0 += r0*wc; w2p1 += r1*wc;
    }
    int o = (t*PMSG+p)*FDIM + f;
    g_TmsgA[o] = make_float4(w0p0*env0, w0p1*env1, w1p0*env0, w1p1*env1);
    g_TmsgB[o] = make_float2(w2p0*env0, w2p1*env1);
}

// ---------------- contraction table (pair-packed, columns remapped to [e3][f]) ----------------
__global__ void k_con_table(const float* __restrict__ Wf)
{
    __shared__ float es[17][FDIM];
    int tid = threadIdx.x;              // 384 threads
    int p0  = blockIdx.x*16, t = blockIdx.y;
    const float step = DMAXC/(PCON-1);
    for (int i = tid; i < 17*FDIM; i += 384) {
        int pl = i / FDIM, k = i % FDIM;
        float d = (p0+pl)*step;
        float o = CUT*k/127.f;
        float x = d - o;
        es[pl][k] = expf(-x*x);
    }
    __syncthreads();
    int src = (tid & 127)*3 + (tid >> 7);
    float acc[17];
    #pragma unroll
    for (int p = 0; p < 17; p++) acc[p] = 0.f;
    const float* Wt = Wf + t*FDIM*384;
    for (int k = 0; k < FDIM; k++) {
        float w = Wt[k*384 + src];
        #pragma unroll
        for (int p = 0; p < 17; p++) acc[p] += es[p][k]*w;
    }
    #pragma unroll
    for (int p = 0; p < 16; p++)
        g_Tcon2[(t*PCON + p0 + p)*384 + tid] = make_float2(acc[p], acc[p+1]);
}

// ---------------- standalone MLP (msg t=0 only), R9 scalar form ----------------
// smem floats: wsW1[16384] | bufA[16384] | bufB[16384] | h_s[1024] | hid_s[1024] = 204800 B
__global__ void __launch_bounds__(512) k_mlp(int hsel,
                      const float* __restrict__ W1, const float* __restrict__ b1,
                      const float* __restrict__ W2, const float* __restrict__ b2, int dst_sel)
{
    extern __shared__ float sm[];
    uint32_t smb = (uint32_t)__cvta_generic_to_shared(sm);
    float* wsW1  = sm;
    float* bufA  = sm + 16384;
    float* bufB  = sm + 32768;
    float* h_s   = sm + 49152;
    float* hid_s = sm + 50176;
    int t = threadIdx.x;                // 512
    int nb = blockIdx.x*8;
    const float4* W2_4 = (const float4*)W2;

    stage64(smb,            (const float4*)W1, t); CP_COMMIT();
    stageW2(smb + 16384*4,  W2_4, 0, t);           CP_COMMIT();
    stageW2(smb + 32768*4,  W2_4, 1, t);           CP_COMMIT();
    const float* hb = g_h[hsel];
    for (int i = t; i < 8*FDIM; i += 512)
        h_s[i] = hb[nb*FDIM + i];

    CP_WAIT(2);
    __syncthreads();
    int g = t & 127, n0 = (t >> 7) * 2;
    {
        float a0 = b1[g], a1 = a0;
        GEMV2(wsW1, h_s, a0, a1)
        hid_s[n0*FDIM+g]     = silu(a0);
        hid_s[(n0+1)*FDIM+g] = silu(a1);
    }
    float A[3][2];
    CP_WAIT(1);
    __syncthreads();
    {
        float a0 = b2[g], a1 = a0;
        GEMV2(bufA, hid_s, a0, a1)
        A[0][0] = a0; A[0][1] = a1;
    }
    __syncthreads();
    stageW2(smb + 16384*4, W2_4, 2, t); CP_COMMIT();
    CP_WAIT(1);
    __syncthreads();
    {
        float a0 = b2[128+g], a1 = a0;
        GEMV2(bufB, hid_s, a0, a1)
        A[1][0] = a0; A[1][1] = a1;
    }
    CP_WAIT(0);
    __syncthreads();
    {
        float a0 = b2[256+g], a1 = a0;
        GEMV2(bufA, hid_s, a0, a1)
        A[2][0] = a0; A[2][1] = a1;
    }
    if (dst_sel == 0) {
        g_phi4[(nb+n0  )*FDIM + g] = make_float4(A[0][0], A[1][0], A[2][0], 0.f);
        g_phi4[(nb+n0+1)*FDIM + g] = make_float4(A[0][1], A[1][1], A[2][1], 0.f);
    } else {
        #pragma unroll
        for (int mm = 0; mm < 3; mm++) {
            int m = mm*128 + g;
            int oi = ((m % 3) << 7) + (m / 3);
            g_phic[(nb+n0  )*384 + oi] = A[mm][0];
            g_phic[(nb+n0+1)*384 + oi] = A[mm][1];
        }
    }
}

// ---------------- edge message pass: packed table + phi4 ----------------
__global__ void __launch_bounds__(128) k_edge(int t, int cur, int nxt)
{
    int i = blockIdx.x, f = threadIdx.x;
    int e0 = g_ptrn[i], e1 = g_ptrn[i+1];
    const float4* TA = g_TmsgA + (size_t)t*PMSG*FDIM;
    const float2* TB = g_TmsgB + (size_t)t*PMSG*FDIM;
    const float4* vcur = g_v[cur];
    const float inv_step = (PMSG-1)/CUT;
    float acch = 0.f, av0 = 0.f, av1 = 0.f, av2 = 0.f;
    for (int q = e0; q < e1; q++) {
        int e = g_csr[q];
        float d = g_ed[e];
        float u = d*inv_step;
        int idx = (int)u; if (idx > PMSG-2) idx = PMSG-2;
        float fr = u - idx;
        float4 Aq = TA[idx*FDIM + f];
        float2 Bq = TB[idx*FDIM + f];
        float w0 = fmaf(fr, Aq.y - Aq.x, Aq.x);
        float w1 = fmaf(fr, Aq.w - Aq.z, Aq.z);
        float w2 = fmaf(fr, Bq.y - Bq.x, Bq.x);
        int pj = g_pj[e];
        float4 ph = g_phi4[pj*FDIM + f];
        float i0 = ph.x*w0, i1 = ph.y*w1, i2 = ph.z*w2;
        float4 uq = g_un[e];
        float4 vj = vcur[pj*FDIM + f];
        acch += i1;
        av0  += i2*uq.x + i0*vj.x;
        av1  += i2*uq.y + i0*vj.y;
        av2  += i2*uq.z + i0*vj.z;
    }
    g_h[nxt][i*FDIM+f] = g_h[cur][i*FDIM+f] + 0.5f*acch;
    float4 vc = vcur[i*FDIM+f];
    g_v[nxt][i*FDIM+f] = make_float4(vc.x + 0.5f*av0, vc.y + 0.5f*av1, vc.z + 0.5f*av2, 0.f);
}

// ---------------- FUSED: update + con-mlp + msg-mlp(t+1), 8 nodes/block, 512 threads ----------------
// 15 weight chunks through 3 rotating cp.async buffers, always 2 in flight.
// smem floats: B0[16384] | B1[16384] | B2[16384] | h_s[1024] | v_s[4096] | vn_s[1024] | hid_s[1024]
//            = 56320 floats = 225280 B
__global__ void __launch_bounds__(512) k_fused(
    const float* __restrict__ U,   const float* __restrict__ Vm,
    const float* __restrict__ uW1, const float* __restrict__ ub1,
    const float* __restrict__ uW2, const float* __restrict__ ub2,
    const float* __restrict__ cW1, const float* __restrict__ cb1,
    const float* __restrict__ cW2, const float* __restrict__ cb2,
    const float* __restrict__ mW1, const float* __restrict__ mb1,
    const float* __restrict__ mW2, const float* __restrict__ mb2,
    int buf, int do_msg)
{
    extern __shared__ float sm[];
    uint32_t smb = (uint32_t)__cvta_generic_to_shared(sm);
    uint32_t sB0 = smb, sB1 = smb + 16384*4, sB2 = smb + 32768*4;
    float*  B0    = sm;
    float*  B1    = sm + 16384;
    float*  B2    = sm + 32768;
    float*  h_s   = sm + 49152;
    float4* v_s   = (float4*)(sm + 50176);
    float*  vn_s  = sm + 54272;
    float*  hid_s = sm + 55296;
    int t = threadIdx.x;                // 512
    int g = t & 127, n0 = (t >> 7) * 2;
    int nb = blockIdx.x*8;
    float*  hb = g_h[buf];
    float4* vb = g_v[buf];
    const float4* uW2_4 = (const float4*)uW2;
    const float4* cW2_4 = (const float4*)cW2;
    const float4* mW2_4 = (const float4*)mW2;

    stage64(sB0, (const float4*)U,  t); CP_COMMIT();   // g0: B0=U
    stage64(sB1, (const float4*)Vm, t); CP_COMMIT();   // g1: B1=V
    stage64(sB2, (const float4*)uW1, t); CP_COMMIT();  // g2: B2=W1a
    for (int i = t; i < 8*FDIM; i += 512) {
        h_s[i] = hb[nb*FDIM + i];
        v_s[i] = vb[nb*FDIM + i];
    }

    // ---- P1: U,V GEMVs fused (B0,B1) ----
    CP_WAIT(1);
    __syncthreads();
    float au0[3] = {0.f,0.f,0.f}, au1[3] = {0.f,0.f,0.f};
    float av0[3] = {0.f,0.f,0.f}, av1[3] = {0.f,0.f,0.f};
    #pragma unroll 4
    for (int f = 0; f < FDIM; f++) {
        float uu = B0[f*FDIM+g];
        float vv = B1[f*FDIM+g];
        float4 x0 = v_s[n0*FDIM + f];
        float4 x1 = v_s[(n0+1)*FDIM + f];
        au0[0] += x0.x*uu; au0[1] += x0.y*uu; au0[2] += x0.z*uu;
        au1[0] += x1.x*uu; au1[1] += x1.y*uu; au1[2] += x1.z*uu;
        av0[0] += x0.x*vv; av0[1] += x0.y*vv; av0[2] += x0.z*vv;
        av1[0] += x1.x*vv; av1[1] += x1.y*vv; av1[2] += x1.z*vv;
    }
    float dot0 = au0[0]*av0[0] + au0[1]*av0[1] + au0[2]*av0[2];
    float dot1 = au1[0]*av1[0] + au1[1]*av1[1] + au1[2]*av1[2];
    vn_s[n0*FDIM + g]     = sqrtf(av0[0]*av0[0] + av0[1]*av0[1] + av0[2]*av0[2] + 1e-15f);
    vn_s[(n0+1)*FDIM + g] = sqrtf(av1[0]*av1[0] + av1[1]*av1[1] + av1[2]*av1[2] + 1e-15f);
    __syncthreads();
    stage64(sB0, ((const float4*)uW1) + 4096, t); CP_COMMIT();  // g3: B0=W1b
    stageW2(sB1, uW2_4, 0, t);                    CP_COMMIT();  // g4: B1=updW2c0

    // ---- P2: updL1 h part (B2=W1a) ----
    CP_WAIT(2);
    __syncthreads();
    float ac0 = ub1[g], ac1 = ac0;
    GEMV2(B2, h_s, ac0, ac1)
    __syncthreads();
    stageW2(sB2, uW2_4, 1, t); CP_COMMIT();                     // g5: B2=updW2c1

    // ---- P3: updL1 vn part (B0=W1b) -> hid ----
    CP_WAIT(2);
    __syncthreads();
    GEMV2(B0, vn_s, ac0, ac1)
    hid_s[n0*FDIM+g]     = silu(ac0);
    hid_s[(n0+1)*FDIM+g] = silu(ac1);
    __syncthreads();
    stageW2(sB0, uW2_4, 2, t); CP_COMMIT();                     // g6: B0=updW2c2

    // ---- P4: updW2c0 (B1) ----
    float A[3][2];
    CP_WAIT(2);
    __syncthreads();
    { float a0 = ub2[g], a1 = a0; GEMV2(B1, hid_s, a0, a1) A[0][0]=a0; A[0][1]=a1; }
    __syncthreads();
    stage64(sB1, (const float4*)cW1, t); CP_COMMIT();           // g7: B1=conW1

    // ---- P5: updW2c1 (B2) ----
    CP_WAIT(2);
    __syncthreads();
    { float a0 = ub2[128+g], a1 = a0; GEMV2(B2, hid_s, a0, a1) A[1][0]=a0; A[1][1]=a1; }
    __syncthreads();
    stageW2(sB2, cW2_4, 0, t); CP_COMMIT();                     // g8: B2=conW2c0

    // ---- P6: updW2c2 (B0) -> finish update, write new h/v, refresh h_s ----
    CP_WAIT(2);
    __syncthreads();
    { float a0 = ub2[256+g], a1 = a0; GEMV2(B0, hid_s, a0, a1) A[2][0]=a0; A[2][1]=a1; }
    float nh0, nh1;
    {
        float ds0 = dot0*A[1][0] + A[2][0];
        float ds1 = dot1*A[1][1] + A[2][1];
        nh0 = h_s[n0*FDIM+g]     + 0.5f*ds0;
        nh1 = h_s[(n0+1)*FDIM+g] + 0.5f*ds1;
        hb[(nb+n0  )*FDIM + g] = nh0;
        hb[(nb+n0+1)*FDIM + g] = nh1;
        float4 vo0 = v_s[n0*FDIM + g];
        float4 vo1 = v_s[(n0+1)*FDIM + g];
        vb[(nb+n0  )*FDIM + g] = make_float4(vo0.x + 0.5f*A[0][0]*au0[0],
                                             vo0.y + 0.5f*A[0][0]*au0[1],
                                             vo0.z + 0.5f*A[0][0]*au0[2], 0.f);
        vb[(nb+n0+1)*FDIM + g] = make_float4(vo1.x + 0.5f*A[0][1]*au1[0],
                                             vo1.y + 0.5f*A[0][1]*au1[1],
                                             vo1.z + 0.5f*A[0][1]*au1[2], 0.f);
        h_s[n0*FDIM+g]     = nh0;     // refresh h_s with post-update h
        h_s[(n0+1)*FDIM+g] = nh1;
    }
    __syncthreads();
    stage64(sB0, (const float4*)mW1, t); CP_COMMIT();           // g9: B0=msgW1

    // ---- P7: conL1 (B1=conW1) on new h -> hid ----
    CP_WAIT(2);
    __syncthreads();
    { float a0 = cb1[g], a1 = a0; GEMV2(B1, h_s, a0, a1)
      hid_s[n0*FDIM+g] = silu(a0); hid_s[(n0+1)*FDIM+g] = silu(a1); }
    __syncthreads();
    stageW2(sB1, cW2_4, 1, t); CP_COMMIT();                     // g10: B1=conW2c1

    // ---- P8: conW2c0 (B2) ----
    CP_WAIT(2);
    __syncthreads();
    { float a0 = cb2[g], a1 = a0; GEMV2(B2, hid_s, a0, a1) A[0][0]=a0; A[0][1]=a1; }
    __syncthreads();
    stageW2(sB2, cW2_4, 2, t); CP_COMMIT();                     // g11: B2=conW2c2

    // ---- P9: conW2c1 (B1) ----
    CP_WAIT(2);
    __syncthreads();
    { float a0 = cb2[128+g], a1 = a0; GEMV2(B1, hid_s, a0, a1) A[1][0]=a0; A[1][1]=a1; }
    __syncthreads();
    stageW2(sB1, mW2_4, 0, t); CP_COMMIT();                     // g12: B1=msgW2c0

    // ---- P10: conW2c2 (B2) -> write g_phic ----
    CP_WAIT(2);
    __syncthreads();
    { float a0 = cb2[256+g], a1 = a0; GEMV2(B2, hid_s, a0, a1) A[2][0]=a0; A[2][1]=a1; }
    #pragma unroll
    for (int mm = 0; mm < 3; mm++) {
        int m = mm*128 + g;
        int oi = ((m % 3) << 7) + (m / 3);
        g_phic[(nb+n0  )*384 + oi] = A[mm][0];
        g_phic[(nb+n0+1)*384 + oi] = A[mm][1];
    }
    __syncthreads();
    stageW2(sB2, mW2_4, 1, t); CP_COMMIT();                     // g13: B2=msgW2c1

    // ---- P11: msgL1 (B0=msgW1) on new h -> hid ----
    CP_WAIT(2);
    __syncthreads();
    { float a0 = mb1[g], a1 = a0; GEMV2(B0, h_s, a0, a1)
      hid_s[n0*FDIM+g] = silu(a0); hid_s[(n0+1)*FDIM+g] = silu(a1); }
    __syncthreads();
    stageW2(sB0, mW2_4, 2, t); CP_COMMIT();                     // g14: B0=msgW2c2

    // ---- P12: msgW2c0 (B1) ----
    CP_WAIT(2);
    __syncthreads();
    { float a0 = mb2[g], a1 = a0; GEMV2(B1, hid_s, a0, a1) A[0][0]=a0; A[0][1]=a1; }

    // ---- P13: msgW2c1 (B2) ----
    CP_WAIT(1);
    __syncthreads();
    { float a0 = mb2[128+g], a1 = a0; GEMV2(B2, hid_s, a0, a1) A[1][0]=a0; A[1][1]=a1; }

    // ---- P14: msgW2c2 (B0) -> write g_phi4 ----
    CP_WAIT(0);
    __syncthreads();
    { float a0 = mb2[256+g], a1 = a0; GEMV2(B0, hid_s, a0, a1) A[2][0]=a0; A[2][1]=a1; }
    if (do_msg) {
        g_phi4[(nb+n0  )*FDIM + g] = make_float4(A[0][0], A[1][0], A[2][0], 0.f);
        g_phi4[(nb+n0+1)*FDIM + g] = make_float4(A[0][1], A[1][1], A[2][1], 0.f);
    }
}

// ---------------- contraction: 4 CG sites per block, 16-atom chunks (1024 blocks) ----------------
__global__ void __launch_bounds__(128) k_contract(int t, int buf,
    const float* __restrict__ bf,
    const float* __restrict__ xyz, const float* __restrict__ cgxyz,
    const float* __restrict__ assign, float* __restrict__ out)
{
    int f  = threadIdx.x;
    int b  = blockIdx.x >> 4;
    int cg0 = (blockIdx.x & 15) << 2;
    int a0 = blockIdx.y << 4;                 // 16 atoms per chunk, gridDim.y = 32
    const float2* Tc = g_Tcon2 + (size_t)t*PCON*384;
    const float4* vbuf = g_v[buf];
    float cx[4], cy[4], cz[4];
    #pragma unroll
    for (int c = 0; c < 4; c++) {
        int base = (b*NCGC + cg0 + c)*3;
        cx[c] = cgxyz[base]; cy[c] = cgxyz[base+1]; cz[c] = cgxyz[base+2];
    }
    float bf0 = bf[f*3+0], bf1 = bf[f*3+1], bf2 = bf[f*3+2];
    const float inv_step = (PCON-1)/DMAXC;
    float hacc[4], v0a[4], v1a[4], v2a[4];
    #pragma unroll
    for (int c = 0; c < 4; c++) { hacc[c]=0.f; v0a[c]=0.f; v1a[c]=0.f; v2a[c]=0.f; }
    for (int aa = 0; aa < 16; aa++) {
        int n = b*NNODES + a0 + aa;
        float px = xyz[3*n], py = xyz[3*n+1], pz = xyz[3*n+2];
        const float* pp = g_phic + n*384;
        float f0 = pp[f], f1 = pp[128+f], f2 = pp[256+f];
        float4 vp = vbuf[n*FDIM + f];
        const float* as = assign + n*NCGC + cg0;
        #pragma unroll
        for (int c = 0; c < 4; c++) {
            float rx = px - cx[c], ry = py - cy[c], rz = pz - cz[c];
            float d = sqrtf(rx*rx + ry*ry + rz*rz);
            float inv_d = 1.f/d;
            float s = as[c];
            float td = d*inv_step;
            int idx = (int)td;
            float fr;
            if (idx > PCON-2) { idx = PCON-2; fr = 1.f; } else fr = td - idx;
            const float2* ba = Tc + idx*384;
            float2 q0 = ba[f], q1 = ba[128+f], q2 = ba[256+f];
            float w0 = fmaf(fr, q0.y - q0.x, q0.x) + bf0;
            float w1 = fmaf(fr, q1.y - q1.x, q1.x) + bf1;
            float w2 = fmaf(fr, q2.y - q2.x, q2.x) + bf2;
            float x0 = w0*f0, x1 = w1*f1, x2 = w2*f2;
            hacc[c] += s*x1;
            v0a[c]  += s*(x2*(rx*inv_d) + x0*vp.x);
            v1a[c]  += s*(x2*(ry*inv_d) + x0*vp.y);
            v2a[c]  += s*(x2*(rz*inv_d) + x0*vp.z);
        }
    }
    #pragma unroll
    for (int c = 0; c < 4; c++) {
        int cc = b*NCGC + cg0 + c;
        atomicAdd(&out[cc*FDIM + f], hacc[c]);
        float* vout = out + BB*NCGC*FDIM + (cc*FDIM + f)*3;
        atomicAdd(vout+0, v0a[c]);
        atomicAdd(vout+1, v1a[c]);
        atomicAdd(vout+2, v2a[c]);
    }
}

// ---------------- host ----------------
#define MLP_SMEM (204800)
#define FUS_SMEM (225280)

extern "C" void kernel_launch(void* const* d_in, const int* in_sizes, int n_in,
                              void* d_out, int out_size)
{
    const float* h_in   = (const float*)d_in[0];
    const float* H_in   = (const float*)d_in[1];
    const float* xyz    = (const float*)d_in[2];
    const float* cgxyz  = (const float*)d_in[3];
    const float* assign = (const float*)d_in[4];
    const int*   nbr    = (const int*)  d_in[6];
    const float* msgW1  = (const float*)d_in[7];
    const float* msgb1  = (const float*)d_in[8];
    const float* msgW2  = (const float*)d_in[9];
    const float* msgb2  = (const float*)d_in[10];
    const float* We     = (const float*)d_in[11];
    const float* be     = (const float*)d_in[12];
    const float* updU   = (const float*)d_in[13];
    const float* updV   = (const float*)d_in[14];
    const float* updW1  = (const float*)d_in[15];
    const float* updb1  = (const float*)d_in[16];
    const float* updW2  = (const float*)d_in[17];
    const float* updb2  = (const float*)d_in[18];
    const float* conWf  = (const float*)d_in[19];
    const float* conbf  = (const float*)d_in[20];
    const float* conW1  = (const float*)d_in[21];
    const float* conb1  = (const float*)d_in[22];
    const float* conW2  = (const float*)d_in[23];
    const float* conb2  = (const float*)d_in[24];
    float* out = (float*)d_out;

    cudaFuncSetAttribute(k_mlp,   cudaFuncAttributeMaxDynamicSharedMemorySize, MLP_SMEM);
    cudaFuncSetAttribute(k_fused, cudaFuncAttributeMaxDynamicSharedMemorySize, FUS_SMEM);

    k_init_geom<<<ETOT/256, 256>>>(h_in, H_in, out, nbr, xyz);          // 1
    k_scan_fill<<<1, BN>>>();                                            // 2
    {
        dim3 gc(PCON/16, NCONVS);
        k_con_table<<<gc, 384>>>(conWf);                                 // 3
    }
    k_mlp<<<BN/8, 512, MLP_SMEM>>>(0, msgW1, msgb1, msgW2, msgb2, 0);    // 4 (profiled)
    {
        dim3 gm(PMSG, NCONVS);
        k_msg_table<<<gm, 128>>>(We, be);                                // 5
    }

    int cur = 0;
    for (int t = 0; t < NCONVS; t++) {
        int nxt = 1 - cur;
        k_edge<<<BN, 128>>>(t, cur, nxt);
        int tm = (t + 1 < NCONVS) ? (t + 1) : 0;   // msg weights for next iter (aliased on last)
        k_fused<<<BN/8, 512, FUS_SMEM>>>(
            updU + t*FDIM*FDIM, updV + t*FDIM*FDIM,
            updW1 + t*2*FDIM*FDIM, updb1 + t*FDIM,
            updW2 + t*FDIM*384,    updb2 + t*384,
            conW1 + t*FDIM*FDIM,   conb1 + t*FDIM,
            conW2 + t*FDIM*384,    conb2 + t*384,
            msgW1 + tm*FDIM*FDIM,  msgb1 + tm*FDIM,
            msgW2 + tm*FDIM*384,   msgb2 + tm*384,
            nxt, (t + 1 < NCONVS) ? 1 : 0);
        dim3 gk(BB*NCGC/4, 32);
        k_contract<<<gk, 128>>>(t, nxt, conbf + t*384, xyz, cgxyz, assign, out);
        cur = nxt;
    }
    (void)in_sizes; (void)n_in; (void)out_size;
}